// round 5
// baseline (speedup 1.0000x reference)
#include <cuda_runtime.h>
#include <cstdint>

// Problem constants (fixed by reference setup_inputs)
#define D_MODEL 1024
#define HEAD    64
#define NHEAD   16
#define ROWS    16384   // B*S
#define NGRP    1024    // ROWS/NHEAD

// ---------------------------------------------------------------------------
// Scratch (device globals — no allocation allowed)
// ---------------------------------------------------------------------------
__device__ __align__(128) float g_qp[ROWS * HEAD];
__device__ __align__(128) float g_kp[ROWS * HEAD];
__device__ __align__(128) float g_vp[ROWS * HEAD];
__device__ __align__(128) float g_x [NGRP * D_MODEL];

// Quantized weights: planes [N, K=1024] int8 (k-major), radix-256 two-digit
__device__ __align__(128) int8_t g_wq1[HEAD * D_MODEL];
__device__ __align__(128) int8_t g_wq0[HEAD * D_MODEL];
__device__ __align__(128) int8_t g_wk1[HEAD * D_MODEL];
__device__ __align__(128) int8_t g_wk0[HEAD * D_MODEL];
__device__ __align__(128) int8_t g_wv1[HEAD * D_MODEL];
__device__ __align__(128) int8_t g_wv0[HEAD * D_MODEL];
__device__ __align__(128) int8_t g_wp1[D_MODEL * D_MODEL];
__device__ __align__(128) int8_t g_wp0[D_MODEL * D_MODEL];
// Per-output-row scales: sBp = s_b * 256 (fold constant), sBi = 1/s_b (quantizer)
__device__ float g_sq_p[HEAD],    g_sq_i[HEAD];
__device__ float g_sk_p[HEAD],    g_sk_i[HEAD];
__device__ float g_sv_p[HEAD],    g_sv_i[HEAD];
__device__ float g_sp_p[D_MODEL], g_sp_i[D_MODEL];

// ---------------------------------------------------------------------------
// PTX helpers (sm_80 baseline features only — safe for compute_103 target)
// ---------------------------------------------------------------------------
__device__ __forceinline__ uint32_t smem_u32(const void* p) {
    uint32_t a;
    asm("{ .reg .u64 t; cvta.to.shared.u64 t, %1; cvt.u32.u64 %0, t; }" : "=r"(a) : "l"(p));
    return a;
}
__device__ __forceinline__ void cp_async16(uint32_t dst, const void* src) {
    asm volatile("cp.async.cg.shared.global [%0], [%1], 16;" :: "r"(dst), "l"(src));
}
#define CP_COMMIT() asm volatile("cp.async.commit_group;")
#define CP_WAIT0()  asm volatile("cp.async.wait_group 0;" ::: "memory")

// s8 IMMA m16n8k32, fresh accumulator (C = 0)
__device__ __forceinline__ void imma_z(int* d, const uint32_t* a, const uint32_t* b) {
    asm volatile(
        "mma.sync.aligned.m16n8k32.row.col.s32.s8.s8.s32 "
        "{%0,%1,%2,%3},{%4,%5,%6,%7},{%8,%9},{%10,%11,%12,%13};"
        : "=r"(d[0]), "=r"(d[1]), "=r"(d[2]), "=r"(d[3])
        : "r"(a[0]), "r"(a[1]), "r"(a[2]), "r"(a[3]), "r"(b[0]), "r"(b[1]),
          "r"(0), "r"(0), "r"(0), "r"(0));
}
// s8 IMMA m16n8k32, accumulate in place
__device__ __forceinline__ void imma_a(int* d, const uint32_t* a, const uint32_t* b) {
    asm volatile(
        "mma.sync.aligned.m16n8k32.row.col.s32.s8.s8.s32 "
        "{%0,%1,%2,%3},{%4,%5,%6,%7},{%8,%9},{%0,%1,%2,%3};"
        : "+r"(d[0]), "+r"(d[1]), "+r"(d[2]), "+r"(d[3])
        : "r"(a[0]), "r"(a[1]), "r"(a[2]), "r"(a[3]), "r"(b[0]), "r"(b[1]));
}
__device__ __forceinline__ uint32_t pack4(int v0, int v1, int v2, int v3) {
    return (uint32_t)(v0 & 255) | ((uint32_t)(v1 & 255) << 8) |
           ((uint32_t)(v2 & 255) << 16) | ((uint32_t)(v3 & 255) << 24);
}

// ---------------------------------------------------------------------------
// Weight prep pass 1: per-column max of W[K=1024, N] -> scales
// ---------------------------------------------------------------------------
__global__ void wcolmax_kernel(const float* __restrict__ W,
                               float* __restrict__ sBp, float* __restrict__ sBi, int N)
{
    int n = blockIdx.x * 256 + threadIdx.x;
    if (n >= N) return;
    float m = 0.f;
    for (int k = 0; k < 1024; k++) m = fmaxf(m, fabsf(W[(size_t)k * N + n]));
    float s  = (m > 0.f) ? (m / 32512.f) : 1.f;
    sBp[n] = s * 256.f;
    sBi[n] = (m > 0.f) ? (32512.f / m) : 0.f;
}

// ---------------------------------------------------------------------------
// Weight prep pass 2: W[K,N] -> B1/B0 planes [N,K] int8 (transpose + quantize)
// ---------------------------------------------------------------------------
__global__ __launch_bounds__(256)
void wtransq_kernel(const float* __restrict__ W, const float* __restrict__ sBi,
                    int8_t* __restrict__ B1, int8_t* __restrict__ B0, int N)
{
    __shared__ float t[32][33];
    const int n0 = blockIdx.x * 32, k0 = blockIdx.y * 32;
    const int tx = threadIdx.x, ty = threadIdx.y;
#pragma unroll
    for (int j = 0; j < 4; j++)
        t[ty + 8 * j][tx] = W[(size_t)(k0 + ty + 8 * j) * N + n0 + tx];
    __syncthreads();
#pragma unroll
    for (int j = 0; j < 4; j++) {
        int n = n0 + ty + 8 * j;
        float inv = sBi[n];
        int ai = __float2int_rn(t[tx][ty + 8 * j] * inv);
        int b1 = (ai + 128) >> 8;
        int b0 = ai - (b1 << 8);
        size_t o = (size_t)n * 1024 + k0 + tx;
        B1[o] = (int8_t)b1;
        B0[o] = (int8_t)b0;
    }
}

// ---------------------------------------------------------------------------
// int8 split GEMM: C[bm:+128, bn:+64] = A[.,1024] @ Bt^T + bias
//   A fp32, quantized on the fly (per-row-per-128-chunk scale, radix-256 digits)
//   Bt pre-quantized int8 planes [N,1024] with per-row scale.
//   D = sA*sB*(65536*a1b1 + 256*(a1b0 + a0b1))   [a0b0 dropped, ~5e-5 rel]
// BM=128, BN=64, BK=128, 256 thr = 8 warps (4M x 2N), warp tile 32x32.
// ---------------------------------------------------------------------------
#define ST_A1 0
#define ST_A0 18432                    // 128*144
#define ST_B1 36864
#define ST_B0 46080                    // +64*144
#define ST_SA 55296                    // 128 floats
#define ST_SIZE 55808
#define SMEM_TOTAL (2 * ST_SIZE)       // 111616

struct GArgs {
    const float*  A;
    const int8_t* B1;
    const int8_t* B0;
    const float*  sBp;   // s_b * 256 per row n
    const float*  bias;
    float*        C;
};

__device__ __forceinline__
void gemm_i8_body(const GArgs& g, int ldc, int bm, int bn, char* sm)
{
    const uint32_t sb = smem_u32(sm);
    const int tid = threadIdx.x;
    const int lane = tid & 31, w = tid >> 5;
    const int gq = lane >> 2, tq = lane & 3;
    const int wm = (w >> 1) * 32, wn = (w & 1) * 32;

    float facc[2][4][4];
#pragma unroll
    for (int mt = 0; mt < 2; mt++)
#pragma unroll
        for (int nt = 0; nt < 4; nt++)
#pragma unroll
            for (int j = 0; j < 4; j++) facc[mt][nt][j] = 0.f;

    // per-column fold scales (s_b * 256)
    float sbv[4][2];
#pragma unroll
    for (int nt = 0; nt < 4; nt++) {
        sbv[nt][0] = __ldg(&g.sBp[bn + wn + nt * 8 + tq * 2]);
        sbv[nt][1] = __ldg(&g.sBp[bn + wn + nt * 8 + tq * 2 + 1]);
    }

    // ---- B tiles via cp.async
    auto cp_B = [&](int ch, int stg) {
        const int k0 = ch * 128;
        const uint32_t b1d = sb + stg * ST_SIZE + ST_B1;
        const uint32_t b0d = sb + stg * ST_SIZE + ST_B0;
        const int r = tid >> 2;
#pragma unroll
        for (int it = 0; it < 2; it++) {
            const int seg = (tid & 3) + 4 * it;
            const uint32_t d = (uint32_t)(r * 144 + seg * 16);
            const size_t s = (size_t)(bn + r) * 1024 + k0 + seg * 16;
            cp_async16(b1d + d, g.B1 + s);
            cp_async16(b0d + d, g.B0 + s);
        }
        CP_COMMIT();
    };

    // ---- load A half (64 rows x 128 cols fp32), quantize, store digits
    auto ldq_A = [&](int ch, int stg, int h) {
        const int k0 = ch * 128;
        float4 aR[8];
#pragma unroll
        for (int p = 0; p < 8; p++) {
            int row = h * 64 + p * 8 + w;
            aR[p] = *(const float4*)&g.A[(size_t)(bm + row) * 1024 + k0 + lane * 4];
        }
        char* st = sm + stg * ST_SIZE;
#pragma unroll
        for (int p = 0; p < 8; p++) {
            const int row = h * 64 + p * 8 + w;
            float4 v = aR[p];
            float m = fmaxf(fmaxf(fabsf(v.x), fabsf(v.y)), fmaxf(fabsf(v.z), fabsf(v.w)));
#pragma unroll
            for (int o = 16; o; o >>= 1) m = fmaxf(m, __shfl_xor_sync(0xFFFFFFFFu, m, o));
            float inv = (m > 0.f) ? (32512.f / m) : 0.f;
            int i0 = __float2int_rn(v.x * inv);
            int i1 = __float2int_rn(v.y * inv);
            int i2 = __float2int_rn(v.z * inv);
            int i3 = __float2int_rn(v.w * inv);
            int h0 = (i0 + 128) >> 8, h1 = (i1 + 128) >> 8;
            int h2 = (i2 + 128) >> 8, h3 = (i3 + 128) >> 8;
            *(uint32_t*)(st + ST_A1 + row * 144 + lane * 4) = pack4(h0, h1, h2, h3);
            *(uint32_t*)(st + ST_A0 + row * 144 + lane * 4) =
                pack4(i0 - (h0 << 8), i1 - (h1 << 8), i2 - (h2 << 8), i3 - (h3 << 8));
            if (lane == 0) *(float*)(st + ST_SA + row * 4) = m * (1.f / 32512.f);
        }
    };

    // ---- MMA + fold for one stage (K = 128, 4 ksteps of k32)
    auto mma_fold = [&](int stg) {
        const char* st = sm + stg * ST_SIZE;
        float sa[2][2];
#pragma unroll
        for (int mt = 0; mt < 2; mt++) {
            sa[mt][0] = *(const float*)(st + ST_SA + (wm + mt * 16 + gq) * 4);
            sa[mt][1] = *(const float*)(st + ST_SA + (wm + mt * 16 + gq + 8) * 4);
        }
#pragma unroll
        for (int ks = 0; ks < 4; ks++) {
            uint32_t fa1[2][4], fa0[2][4], fb1[4][2], fb0[4][2];
#pragma unroll
            for (int mt = 0; mt < 2; mt++) {
                const char* p1 = st + ST_A1 + (wm + mt * 16 + gq) * 144 + ks * 32 + tq * 4;
                const char* p0 = st + ST_A0 + (wm + mt * 16 + gq) * 144 + ks * 32 + tq * 4;
                fa1[mt][0] = *(const uint32_t*)(p1);
                fa1[mt][1] = *(const uint32_t*)(p1 + 8 * 144);
                fa1[mt][2] = *(const uint32_t*)(p1 + 16);
                fa1[mt][3] = *(const uint32_t*)(p1 + 8 * 144 + 16);
                fa0[mt][0] = *(const uint32_t*)(p0);
                fa0[mt][1] = *(const uint32_t*)(p0 + 8 * 144);
                fa0[mt][2] = *(const uint32_t*)(p0 + 16);
                fa0[mt][3] = *(const uint32_t*)(p0 + 8 * 144 + 16);
            }
#pragma unroll
            for (int nt = 0; nt < 4; nt++) {
                const char* p1 = st + ST_B1 + (wn + nt * 8 + gq) * 144 + ks * 32 + tq * 4;
                const char* p0 = st + ST_B0 + (wn + nt * 8 + gq) * 144 + ks * 32 + tq * 4;
                fb1[nt][0] = *(const uint32_t*)(p1);
                fb1[nt][1] = *(const uint32_t*)(p1 + 16);
                fb0[nt][0] = *(const uint32_t*)(p0);
                fb0[nt][1] = *(const uint32_t*)(p0 + 16);
            }
#pragma unroll
            for (int mt = 0; mt < 2; mt++)
#pragma unroll
                for (int nt = 0; nt < 4; nt++) {
                    int aH[4], aM[4];
                    imma_z(aH, fa1[mt], fb1[nt]);
                    imma_z(aM, fa1[mt], fb0[nt]);
                    imma_a(aM, fa0[mt], fb1[nt]);
#pragma unroll
                    for (int j = 0; j < 4; j++) {
                        int vi = (aH[j] << 8) + aM[j];
                        facc[mt][nt][j] = fmaf(sa[mt][j >> 1] * sbv[nt][j & 1],
                                               (float)vi, facc[mt][nt][j]);
                    }
                }
        }
    };

    // ---------------- pipeline (8 chunks of K=128) ----------------
    cp_B(0, 0);
    ldq_A(0, 0, 0);
    ldq_A(0, 0, 1);
    CP_WAIT0();
    __syncthreads();

    for (int ch = 0; ch < 8; ch++) {
        const int cur = ch & 1, nxt = cur ^ 1;
        if (ch < 7) {
            cp_B(ch + 1, nxt);
            ldq_A(ch + 1, nxt, 0);
        }
        mma_fold(cur);
        if (ch < 7) {
            ldq_A(ch + 1, nxt, 1);
            CP_WAIT0();
        }
        __syncthreads();
    }

    // ---------------- epilogue ----------------
#pragma unroll
    for (int mt = 0; mt < 2; mt++) {
        const int row0 = bm + wm + mt * 16 + gq;
#pragma unroll
        for (int nt = 0; nt < 4; nt++) {
            const int col = bn + wn + nt * 8 + tq * 2;
            const float b0 = __ldg(&g.bias[col]);
            const float b1 = __ldg(&g.bias[col + 1]);
            float2 v0 = make_float2(facc[mt][nt][0] + b0, facc[mt][nt][1] + b1);
            float2 v1 = make_float2(facc[mt][nt][2] + b0, facc[mt][nt][3] + b1);
            *(float2*)&g.C[(size_t)row0 * ldc + col]       = v0;
            *(float2*)&g.C[(size_t)(row0 + 8) * ldc + col] = v1;
        }
    }
}

// Merged Q/K/V projections: grid (ROWS/128, 1, 3)
__global__ __launch_bounds__(256)
void gemm3_kernel(GArgs p0, GArgs p1, GArgs p2, int ldc)
{
    extern __shared__ char sm[];
    GArgs p = (blockIdx.z == 0) ? p0 : (blockIdx.z == 1) ? p1 : p2;
    gemm_i8_body(p, ldc, blockIdx.x * 128, blockIdx.y * 64, sm);
}
// Single GEMM: grid (M/128, N/64)
__global__ __launch_bounds__(256)
void gemm1_kernel(GArgs p, int ldc)
{
    extern __shared__ char sm[];
    gemm_i8_body(p, ldc, blockIdx.x * 128, blockIdx.y * 64, sm);
}

// ---------------------------------------------------------------------------
// Attention middle stage (register-tiled). One CTA per group n, 128 threads.
// ---------------------------------------------------------------------------
__global__ __launch_bounds__(128)
void attn_kernel(const float* __restrict__ qp, const float* __restrict__ kp,
                 const float* __restrict__ vp, const int* __restrict__ mask,
                 float* __restrict__ X)
{
    __shared__ float Qs[16 * 64];
    __shared__ float Ks[16 * 64];
    __shared__ float Vs[16 * 64];
    __shared__ float S [64 * 64];

    const int n = blockIdx.x, tid = threadIdx.x;
    const float4* qg = (const float4*)(qp + (size_t)n * NHEAD * HEAD);
    const float4* kg = (const float4*)(kp + (size_t)n * NHEAD * HEAD);
    const float4* vg = (const float4*)(vp + (size_t)n * NHEAD * HEAD);
    float4* Qs4 = (float4*)Qs;
    float4* Ks4 = (float4*)Ks;
    float4* Vs4 = (float4*)Vs;

#pragma unroll
    for (int t = tid; t < 256; t += 128) {
        Qs4[t] = qg[t];
        Ks4[t] = kg[t];
        Vs4[t] = vg[t];
    }
    __syncthreads();

    const int ti = tid >> 3, tj = tid & 7;
    float acc[4][8];
#pragma unroll
    for (int r = 0; r < 4; r++)
#pragma unroll
        for (int c = 0; c < 8; c++) acc[r][c] = 0.f;

#pragma unroll
    for (int hh = 0; hh < 16; hh++) {
        float4 q  = Qs4[hh * 16 + ti];
        float4 ka = Ks4[hh * 16 + tj * 2];
        float4 kb = Ks4[hh * 16 + tj * 2 + 1];
        float qv[4] = {q.x, q.y, q.z, q.w};
        float kv[8] = {ka.x, ka.y, ka.z, ka.w, kb.x, kb.y, kb.z, kb.w};
#pragma unroll
        for (int r = 0; r < 4; r++)
#pragma unroll
            for (int c = 0; c < 8; c++) acc[r][c] += qv[r] * kv[c];
    }
#pragma unroll
    for (int r = 0; r < 4; r++) {
        int i = ti * 4 + r;
#pragma unroll
        for (int c = 0; c < 8; c++) {
            int j = tj * 8 + c;
            float s = acc[r][c] * 0.25f;
            if (__ldg(&mask[i * 64 + j]) == 0) s = -1e30f;
            S[i * 64 + j] = s;
        }
    }
    __syncthreads();

    const int a = tid >> 3, b = tid & 7;
    const float4* S4 = (const float4*)S;
    float acc2[4][2];
#pragma unroll
    for (int r = 0; r < 4; r++) { acc2[r][0] = 0.f; acc2[r][1] = 0.f; }

#pragma unroll
    for (int j4 = 0; j4 < 16; j4++) {
        float4 v0 = Vs4[(b * 2 + 0) * 16 + j4];
        float4 v1 = Vs4[(b * 2 + 1) * 16 + j4];
#pragma unroll
        for (int r = 0; r < 4; r++) {
            float4 sv = S4[(a * 4 + r) * 16 + j4];
            acc2[r][0] += sv.x * v0.x + sv.y * v0.y + sv.z * v0.z + sv.w * v0.w;
            acc2[r][1] += sv.x * v1.x + sv.y * v1.y + sv.z * v1.z + sv.w * v1.w;
        }
    }

    float* Xn = X + (size_t)n * D_MODEL;
#pragma unroll
    for (int r = 0; r < 4; r++)
#pragma unroll
        for (int c = 0; c < 2; c++)
            Xn[(b * 2 + c) * 64 + a * 4 + r] = acc2[r][c];
}

// ---------------------------------------------------------------------------
extern "C" void kernel_launch(void* const* d_in, const int* in_sizes, int n_in,
                              void* d_out, int out_size)
{
    const float* query = (const float*)d_in[0];
    const float* key   = (const float*)d_in[1];
    const float* value = (const float*)d_in[2];
    const int*   mask  = (const int*)  d_in[3];
    const float* Wq    = (const float*)d_in[4];
    const float* bq    = (const float*)d_in[5];
    const float* Wk    = (const float*)d_in[6];
    const float* bk    = (const float*)d_in[7];
    const float* Wv    = (const float*)d_in[8];
    const float* bv    = (const float*)d_in[9];
    const float* Wp    = (const float*)d_in[10];
    const float* bp    = (const float*)d_in[11];
    float* out = (float*)d_out;

    float *qp, *kp, *vp, *xg;
    cudaGetSymbolAddress((void**)&qp, g_qp);
    cudaGetSymbolAddress((void**)&kp, g_kp);
    cudaGetSymbolAddress((void**)&vp, g_vp);
    cudaGetSymbolAddress((void**)&xg, g_x);

    int8_t *wq1, *wq0, *wk1, *wk0, *wv1, *wv0, *wp1, *wp0;
    cudaGetSymbolAddress((void**)&wq1, g_wq1);
    cudaGetSymbolAddress((void**)&wq0, g_wq0);
    cudaGetSymbolAddress((void**)&wk1, g_wk1);
    cudaGetSymbolAddress((void**)&wk0, g_wk0);
    cudaGetSymbolAddress((void**)&wv1, g_wv1);
    cudaGetSymbolAddress((void**)&wv0, g_wv0);
    cudaGetSymbolAddress((void**)&wp1, g_wp1);
    cudaGetSymbolAddress((void**)&wp0, g_wp0);
    float *sqp, *sqi, *skp, *ski, *svp, *svi, *spp, *spi;
    cudaGetSymbolAddress((void**)&sqp, g_sq_p);
    cudaGetSymbolAddress((void**)&sqi, g_sq_i);
    cudaGetSymbolAddress((void**)&skp, g_sk_p);
    cudaGetSymbolAddress((void**)&ski, g_sk_i);
    cudaGetSymbolAddress((void**)&svp, g_sv_p);
    cudaGetSymbolAddress((void**)&svi, g_sv_i);
    cudaGetSymbolAddress((void**)&spp, g_sp_p);
    cudaGetSymbolAddress((void**)&spi, g_sp_i);

    cudaFuncSetAttribute(gemm3_kernel, cudaFuncAttributeMaxDynamicSharedMemorySize, SMEM_TOTAL);
    cudaFuncSetAttribute(gemm1_kernel, cudaFuncAttributeMaxDynamicSharedMemorySize, SMEM_TOTAL);

    // Weight prep: column max -> scales, then transpose + quantize
    wcolmax_kernel<<<1, 256>>>(Wq, sqp, sqi, HEAD);
    wcolmax_kernel<<<1, 256>>>(Wk, skp, ski, HEAD);
    wcolmax_kernel<<<1, 256>>>(Wv, svp, svi, HEAD);
    wcolmax_kernel<<<4, 256>>>(Wp, spp, spi, D_MODEL);
    wtransq_kernel<<<dim3(HEAD / 32, D_MODEL / 32), dim3(32, 8)>>>(Wq, sqi, wq1, wq0, HEAD);
    wtransq_kernel<<<dim3(HEAD / 32, D_MODEL / 32), dim3(32, 8)>>>(Wk, ski, wk1, wk0, HEAD);
    wtransq_kernel<<<dim3(HEAD / 32, D_MODEL / 32), dim3(32, 8)>>>(Wv, svi, wv1, wv0, HEAD);
    wtransq_kernel<<<dim3(D_MODEL / 32, D_MODEL / 32), dim3(32, 8)>>>(Wp, spi, wp1, wp0, D_MODEL);

    // Merged projections: (16384 x 1024) @ (1024 x 64) + bias, x3
    GArgs pq = {query, wq1, wq0, sqp, bq, qp};
    GArgs pk = {key,   wk1, wk0, skp, bk, kp};
    GArgs pv = {value, wv1, wv0, svp, bv, vp};
    gemm3_kernel<<<dim3(ROWS / 128, 1, 3), 256, SMEM_TOTAL>>>(pq, pk, pv, HEAD);

    // Attention middle stage -> X (1024 x 1024)
    attn_kernel<<<NGRP, 128>>>(qp, kp, vp, mask, xg);

    // Output projection: (1024 x 1024) @ (1024 x 1024) + bias
    GArgs pp = {xg, wp1, wp0, spp, bp, out};
    gemm1_kernel<<<dim3(NGRP / 128, D_MODEL / 64), 256, SMEM_TOTAL>>>(pp, D_MODEL);
}

// round 6
// speedup vs baseline: 4.4165x; 4.4165x over previous
#include <cuda_runtime.h>
#include <cuda_fp16.h>
#include <cstdint>

// Problem constants (fixed by reference setup_inputs)
#define D_MODEL 1024
#define HEAD    64
#define NHEAD   16
#define ROWS    16384   // B*S
#define NGRP    1024    // ROWS/NHEAD

// ---------------------------------------------------------------------------
// Scratch (device globals — no allocation allowed)
// ---------------------------------------------------------------------------
__device__ __align__(128) float g_qp[ROWS * HEAD];
__device__ __align__(128) float g_kp[ROWS * HEAD];
__device__ __align__(128) float g_vp[ROWS * HEAD];
__device__ __align__(128) float g_x [NGRP * D_MODEL];

// Two-digit f16 weights, transposed: planes [N, K=1024] (k-major rows)
__device__ __align__(128) __half g_wq_h[HEAD * D_MODEL];
__device__ __align__(128) __half g_wq_l[HEAD * D_MODEL];
__device__ __align__(128) __half g_wk_h[HEAD * D_MODEL];
__device__ __align__(128) __half g_wk_l[HEAD * D_MODEL];
__device__ __align__(128) __half g_wv_h[HEAD * D_MODEL];
__device__ __align__(128) __half g_wv_l[HEAD * D_MODEL];
__device__ __align__(128) __half g_wp_h[D_MODEL * D_MODEL];
__device__ __align__(128) __half g_wp_l[D_MODEL * D_MODEL];

// ---------------------------------------------------------------------------
// PTX helpers (sm_80 baseline features only — safe for compute_103 target)
// ---------------------------------------------------------------------------
__device__ __forceinline__ uint32_t smem_u32(const void* p) {
    uint32_t a;
    asm("{ .reg .u64 t; cvta.to.shared.u64 t, %1; cvt.u32.u64 %0, t; }" : "=r"(a) : "l"(p));
    return a;
}
__device__ __forceinline__ void mma_f16(float* d, const uint32_t* a, const uint32_t* b) {
    asm volatile(
        "mma.sync.aligned.m16n8k16.row.col.f32.f16.f16.f32 "
        "{%0,%1,%2,%3}, {%4,%5,%6,%7}, {%8,%9}, {%0,%1,%2,%3};\n"
        : "+f"(d[0]), "+f"(d[1]), "+f"(d[2]), "+f"(d[3])
        : "r"(a[0]), "r"(a[1]), "r"(a[2]), "r"(a[3]), "r"(b[0]), "r"(b[1]));
}
__device__ __forceinline__ void ldsm_x4(uint32_t* r, uint32_t addr) {
    asm volatile("ldmatrix.sync.aligned.m8n8.x4.shared.b16 {%0,%1,%2,%3}, [%4];"
                 : "=r"(r[0]), "=r"(r[1]), "=r"(r[2]), "=r"(r[3]) : "r"(addr));
}
__device__ __forceinline__ void cp_async16(uint32_t dst, const void* src) {
    asm volatile("cp.async.cg.shared.global [%0], [%1], 16;" :: "r"(dst), "l"(src));
}
#define CP_COMMIT() asm volatile("cp.async.commit_group;")
#define CP_WAIT0()  asm volatile("cp.async.wait_group 0;" ::: "memory")

__device__ __forceinline__ uint32_t f16pack(float x, float y) {
    __half2 h = __floats2half2_rn(x, y);
    return *reinterpret_cast<uint32_t*>(&h);
}

// ---------------------------------------------------------------------------
// Weight prep: W[K,N] fp32 -> Wh/Wl [N,K] f16 two-digit (transpose + split)
// Block (32,8) handles a 32(k) x 32(n) tile. Coalesced reads & writes.
// ---------------------------------------------------------------------------
__global__ __launch_bounds__(256)
void wprep_kernel(const float* __restrict__ W,
                  __half* __restrict__ Bh, __half* __restrict__ Bl, int N)
{
    __shared__ float t[32][33];
    const int n0 = blockIdx.x * 32, k0 = blockIdx.y * 32;
    const int tx = threadIdx.x, ty = threadIdx.y;
#pragma unroll
    for (int j = 0; j < 4; j++)
        t[ty + 8 * j][tx] = W[(size_t)(k0 + ty + 8 * j) * N + n0 + tx];
    __syncthreads();
#pragma unroll
    for (int j = 0; j < 4; j++) {
        float x = t[tx][ty + 8 * j];            // = W[k0+tx][n0+ty+8j]
        __half h = __float2half_rn(x);
        size_t o = (size_t)(n0 + ty + 8 * j) * 1024 + k0 + tx;
        Bh[o] = h;
        Bl[o] = __float2half_rn(x - __half2float(h));
    }
}

// ---------------------------------------------------------------------------
// f16 2-term GEMM: C[bm:+128, bn:+64] = A[.,1024] @ Bt^T + bias
//   A fp32 row-major (lda=1024) -> single f16 digit on the fly.
//   Bt two-digit f16 planes [N,1024] K-major. D = Ah*Bh + Ah*Bl.
// BM=128, BN=64, BK=64, 256 threads = 8 warps (4M x 2N), warp tile 32x32.
// Double-buffered SMEM, cp.async for B, register-prefetched A, ldmatrix frags.
// ---------------------------------------------------------------------------
#define PADK 72                         // f16 elems per smem row (144 B)
#define OFF_A  0
#define OFF_BH (128 * PADK)
#define OFF_BL (128 * PADK + 64 * PADK)
#define STAGE_ELEMS (128 * PADK + 2 * 64 * PADK)       // 18432 halves
#define SM_BYTES (2 * STAGE_ELEMS * 2)                 // 73728

struct GArgs {
    const float* A;
    const __half* Bh;
    const __half* Bl;
    const float* bias;
    float* C;
};

__device__ __forceinline__
void gemm_body(const GArgs& g, int ldc, int bm, int bn, __half* sm)
{
    const uint32_t sb = smem_u32(sm);
    const int tid  = threadIdx.x;
    const int lane = tid & 31, w = tid >> 5;
    const int gq = lane >> 2, tq = lane & 3;
    const int wm = (w >> 1) * 32, wn = (w & 1) * 32;

    // ldmatrix lane addressing components
    const int rowA  = (lane & 15);
    const int colA8 = (lane >> 4) * 8;
    const int rowB  = ((lane >> 4) & 1) * 8 + (lane & 7);
    const int colB8 = ((lane >> 3) & 1) * 8;

    float acc[2][4][4];
#pragma unroll
    for (int mt = 0; mt < 2; mt++)
#pragma unroll
        for (int nt = 0; nt < 4; nt++)
#pragma unroll
            for (int r = 0; r < 4; r++) acc[mt][nt][r] = 0.f;

    float4 aR[8];

    auto load_A_regs = [&](int ch) {
        const int k0 = ch * 64;
#pragma unroll
        for (int p = 0; p < 8; p++) {
            int idx = p * 256 + tid;
            int r = idx >> 4, c4 = idx & 15;
            aR[p] = *(const float4*)&g.A[(size_t)(bm + r) * 1024 + k0 + c4 * 4];
        }
    };
    auto store_A = [&](int stg) {
        __half* A = sm + stg * STAGE_ELEMS + OFF_A;
#pragma unroll
        for (int p = 0; p < 8; p++) {
            int idx = p * 256 + tid;
            int r = idx >> 4, c4 = idx & 15;
            uint32_t h01 = f16pack(aR[p].x, aR[p].y);
            uint32_t h23 = f16pack(aR[p].z, aR[p].w);
            *(uint2*)(A + r * PADK + c4 * 4) = make_uint2(h01, h23);
        }
    };
    auto cp_B = [&](int ch, int stg) {
        const int k0 = ch * 64;
        const uint32_t bh = sb + (stg * STAGE_ELEMS + OFF_BH) * 2;
        const uint32_t bl = sb + (stg * STAGE_ELEMS + OFF_BL) * 2;
#pragma unroll
        for (int p = 0; p < 2; p++) {
            int idx = p * 256 + tid;
            int r = idx >> 3, c8 = idx & 7;
            size_t off = (size_t)(bn + r) * 1024 + k0 + c8 * 8;
            uint32_t d = (uint32_t)(r * 144 + c8 * 16);
            cp_async16(bh + d, g.Bh + off);
            cp_async16(bl + d, g.Bl + off);
        }
        CP_COMMIT();
    };
    auto do_mma = [&](int stg) {
        const uint32_t base = sb + (stg * STAGE_ELEMS) * 2;
        const uint32_t aB  = base + OFF_A * 2;
        const uint32_t bhB = base + OFF_BH * 2;
        const uint32_t blB = base + OFF_BL * 2;
#pragma unroll
        for (int ks = 0; ks < 4; ks++) {
            const int kk = ks * 16;
            uint32_t ah[2][4], bh[4][2], bl[4][2];
#pragma unroll
            for (int mt = 0; mt < 2; mt++) {
                uint32_t off = (uint32_t)((wm + mt * 16 + rowA) * 144 + (kk + colA8) * 2);
                ldsm_x4(ah[mt], aB + off);
            }
#pragma unroll
            for (int p = 0; p < 2; p++) {
                uint32_t off = (uint32_t)((wn + p * 16 + rowB) * 144 + (kk + colB8) * 2);
                uint32_t rh[4], rl[4];
                ldsm_x4(rh, bhB + off);
                ldsm_x4(rl, blB + off);
                bh[2 * p][0] = rh[0]; bh[2 * p][1] = rh[1];
                bh[2 * p + 1][0] = rh[2]; bh[2 * p + 1][1] = rh[3];
                bl[2 * p][0] = rl[0]; bl[2 * p][1] = rl[1];
                bl[2 * p + 1][0] = rl[2]; bl[2 * p + 1][1] = rl[3];
            }
#pragma unroll
            for (int mt = 0; mt < 2; mt++)
#pragma unroll
                for (int nt = 0; nt < 4; nt++) {
                    mma_f16(acc[mt][nt], ah[mt], bh[nt]);
                    mma_f16(acc[mt][nt], ah[mt], bl[nt]);
                }
        }
    };

    // ---------------- pipeline ----------------
    load_A_regs(0);
    cp_B(0, 0);
    store_A(0);
    CP_WAIT0();
    __syncthreads();

    for (int ch = 0; ch < 16; ch++) {
        const int cur = ch & 1;
        if (ch < 15) {
            cp_B(ch + 1, cur ^ 1);
            load_A_regs(ch + 1);
        }
        do_mma(cur);
        if (ch < 15) {
            store_A(cur ^ 1);
            CP_WAIT0();
        }
        __syncthreads();
    }

    // ---------------- epilogue ----------------
#pragma unroll
    for (int mt = 0; mt < 2; mt++) {
        const int row0 = bm + wm + mt * 16 + gq;
#pragma unroll
        for (int nt = 0; nt < 4; nt++) {
            const int col = bn + wn + nt * 8 + tq * 2;
            const float b0 = __ldg(&g.bias[col]);
            const float b1 = __ldg(&g.bias[col + 1]);
            float2 v0 = make_float2(acc[mt][nt][0] + b0, acc[mt][nt][1] + b1);
            float2 v1 = make_float2(acc[mt][nt][2] + b0, acc[mt][nt][3] + b1);
            *(float2*)&g.C[(size_t)row0 * ldc + col]       = v0;
            *(float2*)&g.C[(size_t)(row0 + 8) * ldc + col] = v1;
        }
    }
}

// Merged Q/K/V projections: grid (ROWS/128, 1, 3)
__global__ __launch_bounds__(256)
void gemm3_kernel(GArgs p0, GArgs p1, GArgs p2, int ldc)
{
    extern __shared__ __half sm[];
    GArgs p = (blockIdx.z == 0) ? p0 : (blockIdx.z == 1) ? p1 : p2;
    gemm_body(p, ldc, blockIdx.x * 128, blockIdx.y * 64, sm);
}
// Single GEMM: grid (M/128, N/64)
__global__ __launch_bounds__(256)
void gemm1_kernel(GArgs p, int ldc)
{
    extern __shared__ __half sm[];
    gemm_body(p, ldc, blockIdx.x * 128, blockIdx.y * 64, sm);
}

// ---------------------------------------------------------------------------
// Attention middle stage (register-tiled). One CTA per group n, 128 threads.
//   S[i][j] = 0.25 * sum_hh Qp[16n+hh, i] * Kp[16n+hh, j]   (masked)
//   X[n, h*64 + i] = sum_j S[i][j] * Vp[16n+h, j]
// ---------------------------------------------------------------------------
__global__ __launch_bounds__(128)
void attn_kernel(const float* __restrict__ qp, const float* __restrict__ kp,
                 const float* __restrict__ vp, const int* __restrict__ mask,
                 float* __restrict__ X)
{
    __shared__ float Qs[16 * 64];
    __shared__ float Ks[16 * 64];
    __shared__ float Vs[16 * 64];
    __shared__ float S [64 * 64];

    const int n = blockIdx.x, tid = threadIdx.x;
    const float4* qg = (const float4*)(qp + (size_t)n * NHEAD * HEAD);
    const float4* kg = (const float4*)(kp + (size_t)n * NHEAD * HEAD);
    const float4* vg = (const float4*)(vp + (size_t)n * NHEAD * HEAD);
    float4* Qs4 = (float4*)Qs;
    float4* Ks4 = (float4*)Ks;
    float4* Vs4 = (float4*)Vs;

#pragma unroll
    for (int t = tid; t < 256; t += 128) {
        Qs4[t] = qg[t];
        Ks4[t] = kg[t];
        Vs4[t] = vg[t];
    }
    __syncthreads();

    // Stage 1: S = 0.25 * Q^T K (per-thread 4x8 tile)
    const int ti = tid >> 3, tj = tid & 7;
    float acc[4][8];
#pragma unroll
    for (int r = 0; r < 4; r++)
#pragma unroll
        for (int c = 0; c < 8; c++) acc[r][c] = 0.f;

#pragma unroll
    for (int hh = 0; hh < 16; hh++) {
        float4 q  = Qs4[hh * 16 + ti];
        float4 ka = Ks4[hh * 16 + tj * 2];
        float4 kb = Ks4[hh * 16 + tj * 2 + 1];
        float qv[4] = {q.x, q.y, q.z, q.w};
        float kv[8] = {ka.x, ka.y, ka.z, ka.w, kb.x, kb.y, kb.z, kb.w};
#pragma unroll
        for (int r = 0; r < 4; r++)
#pragma unroll
            for (int c = 0; c < 8; c++) acc[r][c] += qv[r] * kv[c];
    }
#pragma unroll
    for (int r = 0; r < 4; r++) {
        int i = ti * 4 + r;
#pragma unroll
        for (int c = 0; c < 8; c++) {
            int j = tj * 8 + c;
            float s = acc[r][c] * 0.25f;
            if (__ldg(&mask[i * 64 + j]) == 0) s = -1e30f;
            S[i * 64 + j] = s;
        }
    }
    __syncthreads();

    // Stage 2: X[i, h] = S[i,:] . V[h,:]  (per-thread 4i x 2h tile)
    const int a = tid >> 3, b = tid & 7;
    const float4* S4 = (const float4*)S;
    float acc2[4][2];
#pragma unroll
    for (int r = 0; r < 4; r++) { acc2[r][0] = 0.f; acc2[r][1] = 0.f; }

#pragma unroll
    for (int j4 = 0; j4 < 16; j4++) {
        float4 v0 = Vs4[(b * 2 + 0) * 16 + j4];
        float4 v1 = Vs4[(b * 2 + 1) * 16 + j4];
#pragma unroll
        for (int r = 0; r < 4; r++) {
            float4 sv = S4[(a * 4 + r) * 16 + j4];
            acc2[r][0] += sv.x * v0.x + sv.y * v0.y + sv.z * v0.z + sv.w * v0.w;
            acc2[r][1] += sv.x * v1.x + sv.y * v1.y + sv.z * v1.z + sv.w * v1.w;
        }
    }

    float* Xn = X + (size_t)n * D_MODEL;
#pragma unroll
    for (int r = 0; r < 4; r++)
#pragma unroll
        for (int c = 0; c < 2; c++)
            Xn[(b * 2 + c) * 64 + a * 4 + r] = acc2[r][c];
}

// ---------------------------------------------------------------------------
extern "C" void kernel_launch(void* const* d_in, const int* in_sizes, int n_in,
                              void* d_out, int out_size)
{
    const float* query = (const float*)d_in[0];
    const float* key   = (const float*)d_in[1];
    const float* value = (const float*)d_in[2];
    const int*   mask  = (const int*)  d_in[3];
    const float* Wq    = (const float*)d_in[4];
    const float* bq    = (const float*)d_in[5];
    const float* Wk    = (const float*)d_in[6];
    const float* bk    = (const float*)d_in[7];
    const float* Wv    = (const float*)d_in[8];
    const float* bv    = (const float*)d_in[9];
    const float* Wp    = (const float*)d_in[10];
    const float* bp    = (const float*)d_in[11];
    float* out = (float*)d_out;

    float *qp, *kp, *vp, *xg;
    cudaGetSymbolAddress((void**)&qp, g_qp);
    cudaGetSymbolAddress((void**)&kp, g_kp);
    cudaGetSymbolAddress((void**)&vp, g_vp);
    cudaGetSymbolAddress((void**)&xg, g_x);
    __half *wqh, *wql, *wkh, *wkl, *wvh, *wvl, *wph, *wpl;
    cudaGetSymbolAddress((void**)&wqh, g_wq_h);
    cudaGetSymbolAddress((void**)&wql, g_wq_l);
    cudaGetSymbolAddress((void**)&wkh, g_wk_h);
    cudaGetSymbolAddress((void**)&wkl, g_wk_l);
    cudaGetSymbolAddress((void**)&wvh, g_wv_h);
    cudaGetSymbolAddress((void**)&wvl, g_wv_l);
    cudaGetSymbolAddress((void**)&wph, g_wp_h);
    cudaGetSymbolAddress((void**)&wpl, g_wp_l);

    cudaFuncSetAttribute(gemm3_kernel, cudaFuncAttributeMaxDynamicSharedMemorySize, SM_BYTES);
    cudaFuncSetAttribute(gemm1_kernel, cudaFuncAttributeMaxDynamicSharedMemorySize, SM_BYTES);

    // Weight prep (tiled transpose + f16 two-digit split)
    wprep_kernel<<<dim3(HEAD / 32, D_MODEL / 32), dim3(32, 8)>>>(Wq, wqh, wql, HEAD);
    wprep_kernel<<<dim3(HEAD / 32, D_MODEL / 32), dim3(32, 8)>>>(Wk, wkh, wkl, HEAD);
    wprep_kernel<<<dim3(HEAD / 32, D_MODEL / 32), dim3(32, 8)>>>(Wv, wvh, wvl, HEAD);
    wprep_kernel<<<dim3(D_MODEL / 32, D_MODEL / 32), dim3(32, 8)>>>(Wp, wph, wpl, D_MODEL);

    // Merged projections: (16384 x 1024) @ (1024 x 64) + bias, x3
    GArgs pq = {query, wqh, wql, bq, qp};
    GArgs pk = {key,   wkh, wkl, bk, kp};
    GArgs pv = {value, wvh, wvl, bv, vp};
    gemm3_kernel<<<dim3(ROWS / 128, 1, 3), 256, SM_BYTES>>>(pq, pk, pv, HEAD);

    // Attention middle stage -> X (1024 x 1024)
    attn_kernel<<<NGRP, 128>>>(qp, kp, vp, mask, xg);

    // Output projection: (1024 x 1024) @ (1024 x 1024) + bias
    GArgs pp = {xg, wph, wpl, bp, out};
    gemm1_kernel<<<dim3(NGRP / 128, D_MODEL / 64), 256, SM_BYTES>>>(pp, D_MODEL);
}

// round 7
// speedup vs baseline: 4.6093x; 1.0436x over previous
#include <cuda_runtime.h>
#include <cuda_fp16.h>
#include <cstdint>

// Problem constants (fixed by reference setup_inputs)
#define D_MODEL 1024
#define HEAD    64
#define NHEAD   16
#define ROWS    16384   // B*S
#define NGRP    1024    // ROWS/NHEAD

// ---------------------------------------------------------------------------
// Scratch (device globals — no allocation allowed)
// ---------------------------------------------------------------------------
__device__ __align__(128) float g_qp[ROWS * HEAD];
__device__ __align__(128) float g_kp[ROWS * HEAD];
__device__ __align__(128) float g_vp[ROWS * HEAD];
__device__ __align__(128) float g_x [NGRP * D_MODEL];

// Single-digit f16 weights, transposed: [N, K=1024] (k-major rows)
__device__ __align__(128) __half g_wq[HEAD * D_MODEL];
__device__ __align__(128) __half g_wk[HEAD * D_MODEL];
__device__ __align__(128) __half g_wv[HEAD * D_MODEL];
__device__ __align__(128) __half g_wp[D_MODEL * D_MODEL];

// ---------------------------------------------------------------------------
// PTX helpers (sm_80 baseline features only — safe for compute_103 target)
// ---------------------------------------------------------------------------
__device__ __forceinline__ uint32_t smem_u32(const void* p) {
    uint32_t a;
    asm("{ .reg .u64 t; cvta.to.shared.u64 t, %1; cvt.u32.u64 %0, t; }" : "=r"(a) : "l"(p));
    return a;
}
__device__ __forceinline__ void mma_f16(float* d, const uint32_t* a, const uint32_t* b) {
    asm volatile(
        "mma.sync.aligned.m16n8k16.row.col.f32.f16.f16.f32 "
        "{%0,%1,%2,%3}, {%4,%5,%6,%7}, {%8,%9}, {%0,%1,%2,%3};\n"
        : "+f"(d[0]), "+f"(d[1]), "+f"(d[2]), "+f"(d[3])
        : "r"(a[0]), "r"(a[1]), "r"(a[2]), "r"(a[3]), "r"(b[0]), "r"(b[1]));
}
__device__ __forceinline__ void ldsm_x4(uint32_t* r, uint32_t addr) {
    asm volatile("ldmatrix.sync.aligned.m8n8.x4.shared.b16 {%0,%1,%2,%3}, [%4];"
                 : "=r"(r[0]), "=r"(r[1]), "=r"(r[2]), "=r"(r[3]) : "r"(addr));
}
__device__ __forceinline__ void cp_async16(uint32_t dst, const void* src) {
    asm volatile("cp.async.cg.shared.global [%0], [%1], 16;" :: "r"(dst), "l"(src));
}
#define CP_COMMIT() asm volatile("cp.async.commit_group;")
#define CP_WAIT0()  asm volatile("cp.async.wait_group 0;" ::: "memory")

__device__ __forceinline__ uint32_t f16pack(float x, float y) {
    __half2 h = __floats2half2_rn(x, y);
    return *reinterpret_cast<uint32_t*>(&h);
}

// ---------------------------------------------------------------------------
// Weight prep: W[K,N] fp32 -> Wt [N,K] f16 (transpose + round)
// Block (32,8) handles a 32(k) x 32(n) tile. Coalesced reads & writes.
// ---------------------------------------------------------------------------
__global__ __launch_bounds__(256)
void wprep_kernel(const float* __restrict__ W, __half* __restrict__ Bt, int N)
{
    __shared__ float t[32][33];
    const int n0 = blockIdx.x * 32, k0 = blockIdx.y * 32;
    const int tx = threadIdx.x, ty = threadIdx.y;
#pragma unroll
    for (int j = 0; j < 4; j++)
        t[ty + 8 * j][tx] = W[(size_t)(k0 + ty + 8 * j) * N + n0 + tx];
    __syncthreads();
#pragma unroll
    for (int j = 0; j < 4; j++) {
        size_t o = (size_t)(n0 + ty + 8 * j) * 1024 + k0 + tx;
        Bt[o] = __float2half_rn(t[tx][ty + 8 * j]);
    }
}

// ---------------------------------------------------------------------------
// f16 GEMM: C[bm:+128, bn:+64] = A[.,1024] @ Bt^T + bias
//   A fp32 row-major (lda=1024) -> f16 on the fly. Bt f16 [N,1024] K-major.
// BM=128, BN=64, BK=64, 256 threads = 8 warps (4M x 2N), warp tile 32x32.
// Double-buffered SMEM, cp.async for B, register-prefetched A, ldmatrix frags.
// ---------------------------------------------------------------------------
#define PADK 72                         // f16 elems per smem row (144 B)
#define OFF_A  0
#define OFF_B  (128 * PADK)
#define STAGE_ELEMS (128 * PADK + 64 * PADK)           // 13824 halves
#define SM_BYTES (2 * STAGE_ELEMS * 2)                 // 55296

struct GArgs {
    const float* A;
    const __half* B;
    const float* bias;
    float* C;
};

__device__ __forceinline__
void gemm_body(const GArgs& g, int ldc, int bm, int bn, __half* sm)
{
    const uint32_t sb = smem_u32(sm);
    const int tid  = threadIdx.x;
    const int lane = tid & 31, w = tid >> 5;
    const int gq = lane >> 2, tq = lane & 3;
    const int wm = (w >> 1) * 32, wn = (w & 1) * 32;

    // ldmatrix lane addressing components
    const int rowA  = (lane & 15);
    const int colA8 = (lane >> 4) * 8;
    const int rowB  = ((lane >> 4) & 1) * 8 + (lane & 7);
    const int colB8 = ((lane >> 3) & 1) * 8;

    float acc[2][4][4];
#pragma unroll
    for (int mt = 0; mt < 2; mt++)
#pragma unroll
        for (int nt = 0; nt < 4; nt++)
#pragma unroll
            for (int r = 0; r < 4; r++) acc[mt][nt][r] = 0.f;

    float4 aR[8];

    auto load_A_regs = [&](int ch) {
        const int k0 = ch * 64;
#pragma unroll
        for (int p = 0; p < 8; p++) {
            int idx = p * 256 + tid;
            int r = idx >> 4, c4 = idx & 15;
            aR[p] = *(const float4*)&g.A[(size_t)(bm + r) * 1024 + k0 + c4 * 4];
        }
    };
    auto store_A = [&](int stg) {
        __half* A = sm + stg * STAGE_ELEMS + OFF_A;
#pragma unroll
        for (int p = 0; p < 8; p++) {
            int idx = p * 256 + tid;
            int r = idx >> 4, c4 = idx & 15;
            uint32_t h01 = f16pack(aR[p].x, aR[p].y);
            uint32_t h23 = f16pack(aR[p].z, aR[p].w);
            *(uint2*)(A + r * PADK + c4 * 4) = make_uint2(h01, h23);
        }
    };
    auto cp_B = [&](int ch, int stg) {
        const int k0 = ch * 64;
        const uint32_t bd = sb + (stg * STAGE_ELEMS + OFF_B) * 2;
#pragma unroll
        for (int p = 0; p < 2; p++) {
            int idx = p * 256 + tid;
            int r = idx >> 3, c8 = idx & 7;
            size_t off = (size_t)(bn + r) * 1024 + k0 + c8 * 8;
            cp_async16(bd + (uint32_t)(r * 144 + c8 * 16), g.B + off);
        }
        CP_COMMIT();
    };
    auto do_mma = [&](int stg) {
        const uint32_t base = sb + (stg * STAGE_ELEMS) * 2;
        const uint32_t aB = base + OFF_A * 2;
        const uint32_t bB = base + OFF_B * 2;
#pragma unroll
        for (int ks = 0; ks < 4; ks++) {
            const int kk = ks * 16;
            uint32_t ah[2][4], bh[4][2];
#pragma unroll
            for (int mt = 0; mt < 2; mt++) {
                uint32_t off = (uint32_t)((wm + mt * 16 + rowA) * 144 + (kk + colA8) * 2);
                ldsm_x4(ah[mt], aB + off);
            }
#pragma unroll
            for (int p = 0; p < 2; p++) {
                uint32_t off = (uint32_t)((wn + p * 16 + rowB) * 144 + (kk + colB8) * 2);
                uint32_t rh[4];
                ldsm_x4(rh, bB + off);
                bh[2 * p][0] = rh[0]; bh[2 * p][1] = rh[1];
                bh[2 * p + 1][0] = rh[2]; bh[2 * p + 1][1] = rh[3];
            }
#pragma unroll
            for (int mt = 0; mt < 2; mt++)
#pragma unroll
                for (int nt = 0; nt < 4; nt++)
                    mma_f16(acc[mt][nt], ah[mt], bh[nt]);
        }
    };

    // ---------------- pipeline ----------------
    load_A_regs(0);
    cp_B(0, 0);
    store_A(0);
    CP_WAIT0();
    __syncthreads();

    for (int ch = 0; ch < 16; ch++) {
        const int cur = ch & 1;
        if (ch < 15) {
            cp_B(ch + 1, cur ^ 1);
            load_A_regs(ch + 1);
        }
        do_mma(cur);
        if (ch < 15) {
            store_A(cur ^ 1);
            CP_WAIT0();
        }
        __syncthreads();
    }

    // ---------------- epilogue ----------------
#pragma unroll
    for (int mt = 0; mt < 2; mt++) {
        const int row0 = bm + wm + mt * 16 + gq;
#pragma unroll
        for (int nt = 0; nt < 4; nt++) {
            const int col = bn + wn + nt * 8 + tq * 2;
            const float b0 = __ldg(&g.bias[col]);
            const float b1 = __ldg(&g.bias[col + 1]);
            float2 v0 = make_float2(acc[mt][nt][0] + b0, acc[mt][nt][1] + b1);
            float2 v1 = make_float2(acc[mt][nt][2] + b0, acc[mt][nt][3] + b1);
            *(float2*)&g.C[(size_t)row0 * ldc + col]       = v0;
            *(float2*)&g.C[(size_t)(row0 + 8) * ldc + col] = v1;
        }
    }
}

// Merged Q/K/V projections: grid (ROWS/128, 1, 3)
__global__ __launch_bounds__(256)
void gemm3_kernel(GArgs p0, GArgs p1, GArgs p2, int ldc)
{
    extern __shared__ __half sm[];
    GArgs p = (blockIdx.z == 0) ? p0 : (blockIdx.z == 1) ? p1 : p2;
    gemm_body(p, ldc, blockIdx.x * 128, blockIdx.y * 64, sm);
}
// Single GEMM: grid (M/128, N/64)
__global__ __launch_bounds__(256)
void gemm1_kernel(GArgs p, int ldc)
{
    extern __shared__ __half sm[];
    gemm_body(p, ldc, blockIdx.x * 128, blockIdx.y * 64, sm);
}

// ---------------------------------------------------------------------------
// Attention middle stage (register-tiled). One CTA per group n, 128 threads.
//   S[i][j] = 0.25 * sum_hh Qp[16n+hh, i] * Kp[16n+hh, j]   (masked)
//   X[n, h*64 + i] = sum_j S[i][j] * Vp[16n+h, j]
// ---------------------------------------------------------------------------
__global__ __launch_bounds__(128)
void attn_kernel(const float* __restrict__ qp, const float* __restrict__ kp,
                 const float* __restrict__ vp, const int* __restrict__ mask,
                 float* __restrict__ X)
{
    __shared__ float Qs[16 * 64];
    __shared__ float Ks[16 * 64];
    __shared__ float Vs[16 * 64];
    __shared__ float S [64 * 64];

    const int n = blockIdx.x, tid = threadIdx.x;
    const float4* qg = (const float4*)(qp + (size_t)n * NHEAD * HEAD);
    const float4* kg = (const float4*)(kp + (size_t)n * NHEAD * HEAD);
    const float4* vg = (const float4*)(vp + (size_t)n * NHEAD * HEAD);
    float4* Qs4 = (float4*)Qs;
    float4* Ks4 = (float4*)Ks;
    float4* Vs4 = (float4*)Vs;

#pragma unroll
    for (int t = tid; t < 256; t += 128) {
        Qs4[t] = qg[t];
        Ks4[t] = kg[t];
        Vs4[t] = vg[t];
    }
    __syncthreads();

    // Stage 1: S = 0.25 * Q^T K (per-thread 4x8 tile)
    const int ti = tid >> 3, tj = tid & 7;
    float acc[4][8];
#pragma unroll
    for (int r = 0; r < 4; r++)
#pragma unroll
        for (int c = 0; c < 8; c++) acc[r][c] = 0.f;

#pragma unroll
    for (int hh = 0; hh < 16; hh++) {
        float4 q  = Qs4[hh * 16 + ti];
        float4 ka = Ks4[hh * 16 + tj * 2];
        float4 kb = Ks4[hh * 16 + tj * 2 + 1];
        float qv[4] = {q.x, q.y, q.z, q.w};
        float kv[8] = {ka.x, ka.y, ka.z, ka.w, kb.x, kb.y, kb.z, kb.w};
#pragma unroll
        for (int r = 0; r < 4; r++)
#pragma unroll
            for (int c = 0; c < 8; c++) acc[r][c] += qv[r] * kv[c];
    }
#pragma unroll
    for (int r = 0; r < 4; r++) {
        int i = ti * 4 + r;
#pragma unroll
        for (int c = 0; c < 8; c++) {
            int j = tj * 8 + c;
            float s = acc[r][c] * 0.25f;
            if (__ldg(&mask[i * 64 + j]) == 0) s = -1e30f;
            S[i * 64 + j] = s;
        }
    }
    __syncthreads();

    // Stage 2: X[i, h] = S[i,:] . V[h,:]  (per-thread 4i x 2h tile)
    const int a = tid >> 3, b = tid & 7;
    const float4* S4 = (const float4*)S;
    float acc2[4][2];
#pragma unroll
    for (int r = 0; r < 4; r++) { acc2[r][0] = 0.f; acc2[r][1] = 0.f; }

#pragma unroll
    for (int j4 = 0; j4 < 16; j4++) {
        float4 v0 = Vs4[(b * 2 + 0) * 16 + j4];
        float4 v1 = Vs4[(b * 2 + 1) * 16 + j4];
#pragma unroll
        for (int r = 0; r < 4; r++) {
            float4 sv = S4[(a * 4 + r) * 16 + j4];
            acc2[r][0] += sv.x * v0.x + sv.y * v0.y + sv.z * v0.z + sv.w * v0.w;
            acc2[r][1] += sv.x * v1.x + sv.y * v1.y + sv.z * v1.z + sv.w * v1.w;
        }
    }

    float* Xn = X + (size_t)n * D_MODEL;
#pragma unroll
    for (int r = 0; r < 4; r++)
#pragma unroll
        for (int c = 0; c < 2; c++)
            Xn[(b * 2 + c) * 64 + a * 4 + r] = acc2[r][c];
}

// ---------------------------------------------------------------------------
extern "C" void kernel_launch(void* const* d_in, const int* in_sizes, int n_in,
                              void* d_out, int out_size)
{
    const float* query = (const float*)d_in[0];
    const float* key   = (const float*)d_in[1];
    const float* value = (const float*)d_in[2];
    const int*   mask  = (const int*)  d_in[3];
    const float* Wq    = (const float*)d_in[4];
    const float* bq    = (const float*)d_in[5];
    const float* Wk    = (const float*)d_in[6];
    const float* bk    = (const float*)d_in[7];
    const float* Wv    = (const float*)d_in[8];
    const float* bv    = (const float*)d_in[9];
    const float* Wp    = (const float*)d_in[10];
    const float* bp    = (const float*)d_in[11];
    float* out = (float*)d_out;

    float *qp, *kp, *vp, *xg;
    cudaGetSymbolAddress((void**)&qp, g_qp);
    cudaGetSymbolAddress((void**)&kp, g_kp);
    cudaGetSymbolAddress((void**)&vp, g_vp);
    cudaGetSymbolAddress((void**)&xg, g_x);
    __half *wq, *wk, *wv, *wp;
    cudaGetSymbolAddress((void**)&wq, g_wq);
    cudaGetSymbolAddress((void**)&wk, g_wk);
    cudaGetSymbolAddress((void**)&wv, g_wv);
    cudaGetSymbolAddress((void**)&wp, g_wp);

    cudaFuncSetAttribute(gemm3_kernel, cudaFuncAttributeMaxDynamicSharedMemorySize, SM_BYTES);
    cudaFuncSetAttribute(gemm1_kernel, cudaFuncAttributeMaxDynamicSharedMemorySize, SM_BYTES);

    // Weight prep (tiled transpose + f16 round)
    wprep_kernel<<<dim3(HEAD / 32, D_MODEL / 32), dim3(32, 8)>>>(Wq, wq, HEAD);
    wprep_kernel<<<dim3(HEAD / 32, D_MODEL / 32), dim3(32, 8)>>>(Wk, wk, HEAD);
    wprep_kernel<<<dim3(HEAD / 32, D_MODEL / 32), dim3(32, 8)>>>(Wv, wv, HEAD);
    wprep_kernel<<<dim3(D_MODEL / 32, D_MODEL / 32), dim3(32, 8)>>>(Wp, wp, D_MODEL);

    // Merged projections: (16384 x 1024) @ (1024 x 64) + bias, x3
    GArgs pq = {query, wq, bq, qp};
    GArgs pk = {key,   wk, bk, kp};
    GArgs pv = {value, wv, bv, vp};
    gemm3_kernel<<<dim3(ROWS / 128, 1, 3), 256, SM_BYTES>>>(pq, pk, pv, HEAD);

    // Attention middle stage -> X (1024 x 1024)
    attn_kernel<<<NGRP, 128>>>(qp, kp, vp, mask, xg);

    // Output projection: (1024 x 1024) @ (1024 x 1024) + bias
    GArgs pp = {xg, wp, bp, out};
    gemm1_kernel<<<dim3(NGRP / 128, D_MODEL / 64), 256, SM_BYTES>>>(pp, D_MODEL);
}

// round 8
// speedup vs baseline: 5.9849x; 1.2985x over previous
#include <cuda_runtime.h>
#include <cuda_fp16.h>
#include <cstdint>

// Problem constants (fixed by reference setup_inputs)
#define D_MODEL 1024
#define HEAD    64
#define NHEAD   16
#define ROWS    16384   // B*S
#define NGRP    1024    // ROWS/NHEAD

// ---------------------------------------------------------------------------
// Scratch (device globals — no allocation allowed)
// ---------------------------------------------------------------------------
__device__ __align__(128) float g_qp[ROWS * HEAD];
__device__ __align__(128) float g_kp[ROWS * HEAD];
__device__ __align__(128) float g_vp[ROWS * HEAD];
__device__ __align__(128) float g_x [NGRP * D_MODEL];

// Single-digit f16 weights, transposed: [N, K=1024] (k-major rows)
__device__ __align__(128) __half g_wq[HEAD * D_MODEL];
__device__ __align__(128) __half g_wk[HEAD * D_MODEL];
__device__ __align__(128) __half g_wv[HEAD * D_MODEL];
__device__ __align__(128) __half g_wp[D_MODEL * D_MODEL];

// ---------------------------------------------------------------------------
// PTX helpers (sm_80 baseline features only — safe for compute_103 target)
// ---------------------------------------------------------------------------
__device__ __forceinline__ uint32_t smem_u32(const void* p) {
    uint32_t a;
    asm("{ .reg .u64 t; cvta.to.shared.u64 t, %1; cvt.u32.u64 %0, t; }" : "=r"(a) : "l"(p));
    return a;
}
__device__ __forceinline__ void mma_f16(float* d, const uint32_t* a, const uint32_t* b) {
    asm volatile(
        "mma.sync.aligned.m16n8k16.row.col.f32.f16.f16.f32 "
        "{%0,%1,%2,%3}, {%4,%5,%6,%7}, {%8,%9}, {%0,%1,%2,%3};\n"
        : "+f"(d[0]), "+f"(d[1]), "+f"(d[2]), "+f"(d[3])
        : "r"(a[0]), "r"(a[1]), "r"(a[2]), "r"(a[3]), "r"(b[0]), "r"(b[1]));
}
__device__ __forceinline__ void ldsm_x4(uint32_t* r, uint32_t addr) {
    asm volatile("ldmatrix.sync.aligned.m8n8.x4.shared.b16 {%0,%1,%2,%3}, [%4];"
                 : "=r"(r[0]), "=r"(r[1]), "=r"(r[2]), "=r"(r[3]) : "r"(addr));
}
__device__ __forceinline__ void cp_async16(uint32_t dst, const void* src) {
    asm volatile("cp.async.cg.shared.global [%0], [%1], 16;" :: "r"(dst), "l"(src));
}
#define CP_COMMIT() asm volatile("cp.async.commit_group;")
#define CP_WAIT0()  asm volatile("cp.async.wait_group 0;" ::: "memory")

__device__ __forceinline__ uint32_t f16pack(float x, float y) {
    __half2 h = __floats2half2_rn(x, y);
    return *reinterpret_cast<uint32_t*>(&h);
}

// ---------------------------------------------------------------------------
// Weight prep: W[K,N] fp32 -> Wt [N,K] f16 (transpose + round)
// ---------------------------------------------------------------------------
__device__ __forceinline__
void wprep_body(const float* __restrict__ W, __half* __restrict__ Bt, int N)
{
    __shared__ float t[32][33];
    const int n0 = blockIdx.x * 32, k0 = blockIdx.y * 32;
    const int tx = threadIdx.x, ty = threadIdx.y;
#pragma unroll
    for (int j = 0; j < 4; j++)
        t[ty + 8 * j][tx] = W[(size_t)(k0 + ty + 8 * j) * N + n0 + tx];
    __syncthreads();
#pragma unroll
    for (int j = 0; j < 4; j++) {
        size_t o = (size_t)(n0 + ty + 8 * j) * 1024 + k0 + tx;
        Bt[o] = __float2half_rn(t[tx][ty + 8 * j]);
    }
}
__global__ __launch_bounds__(256)
void wprep3_kernel(const float* W0, __half* B0, const float* W1, __half* B1,
                   const float* W2, __half* B2)
{
    if (blockIdx.z == 0)      wprep_body(W0, B0, HEAD);
    else if (blockIdx.z == 1) wprep_body(W1, B1, HEAD);
    else                      wprep_body(W2, B2, HEAD);
}
__global__ __launch_bounds__(256)
void wprep1_kernel(const float* W, __half* Bt) { wprep_body(W, Bt, D_MODEL); }

// ---------------------------------------------------------------------------
// f16 GEMM: C[bm:+128, bn:+64] = A[.,1024] @ Bt^T + bias
// BM=128, BN=64, BK=64, 256 threads = 8 warps (4M x 2N), warp tile 32x32.
// ---------------------------------------------------------------------------
#define PADK 72                         // f16 elems per smem row (144 B)
#define OFF_A  0
#define OFF_B  (128 * PADK)
#define STAGE_ELEMS (128 * PADK + 64 * PADK)           // 13824 halves
#define SM_BYTES (2 * STAGE_ELEMS * 2)                 // 55296

struct GArgs {
    const float* A;
    const __half* B;
    const float* bias;
    float* C;
};

__device__ __forceinline__
void gemm_body(const GArgs& g, int ldc, int bm, int bn, __half* sm)
{
    const uint32_t sb = smem_u32(sm);
    const int tid  = threadIdx.x;
    const int lane = tid & 31, w = tid >> 5;
    const int gq = lane >> 2, tq = lane & 3;
    const int wm = (w >> 1) * 32, wn = (w & 1) * 32;

    const int rowA  = (lane & 15);
    const int colA8 = (lane >> 4) * 8;
    const int rowB  = ((lane >> 4) & 1) * 8 + (lane & 7);
    const int colB8 = ((lane >> 3) & 1) * 8;

    float acc[2][4][4];
#pragma unroll
    for (int mt = 0; mt < 2; mt++)
#pragma unroll
        for (int nt = 0; nt < 4; nt++)
#pragma unroll
            for (int r = 0; r < 4; r++) acc[mt][nt][r] = 0.f;

    float4 aR[8];

    auto load_A_regs = [&](int ch) {
        const int k0 = ch * 64;
#pragma unroll
        for (int p = 0; p < 8; p++) {
            int idx = p * 256 + tid;
            int r = idx >> 4, c4 = idx & 15;
            aR[p] = *(const float4*)&g.A[(size_t)(bm + r) * 1024 + k0 + c4 * 4];
        }
    };
    auto store_A = [&](int stg) {
        __half* A = sm + stg * STAGE_ELEMS + OFF_A;
#pragma unroll
        for (int p = 0; p < 8; p++) {
            int idx = p * 256 + tid;
            int r = idx >> 4, c4 = idx & 15;
            uint32_t h01 = f16pack(aR[p].x, aR[p].y);
            uint32_t h23 = f16pack(aR[p].z, aR[p].w);
            *(uint2*)(A + r * PADK + c4 * 4) = make_uint2(h01, h23);
        }
    };
    auto cp_B = [&](int ch, int stg) {
        const int k0 = ch * 64;
        const uint32_t bd = sb + (stg * STAGE_ELEMS + OFF_B) * 2;
#pragma unroll
        for (int p = 0; p < 2; p++) {
            int idx = p * 256 + tid;
            int r = idx >> 3, c8 = idx & 7;
            size_t off = (size_t)(bn + r) * 1024 + k0 + c8 * 8;
            cp_async16(bd + (uint32_t)(r * 144 + c8 * 16), g.B + off);
        }
        CP_COMMIT();
    };
    auto do_mma = [&](int stg) {
        const uint32_t base = sb + (stg * STAGE_ELEMS) * 2;
        const uint32_t aB = base + OFF_A * 2;
        const uint32_t bB = base + OFF_B * 2;
#pragma unroll
        for (int ks = 0; ks < 4; ks++) {
            const int kk = ks * 16;
            uint32_t ah[2][4], bh[4][2];
#pragma unroll
            for (int mt = 0; mt < 2; mt++) {
                uint32_t off = (uint32_t)((wm + mt * 16 + rowA) * 144 + (kk + colA8) * 2);
                ldsm_x4(ah[mt], aB + off);
            }
#pragma unroll
            for (int p = 0; p < 2; p++) {
                uint32_t off = (uint32_t)((wn + p * 16 + rowB) * 144 + (kk + colB8) * 2);
                uint32_t rh[4];
                ldsm_x4(rh, bB + off);
                bh[2 * p][0] = rh[0]; bh[2 * p][1] = rh[1];
                bh[2 * p + 1][0] = rh[2]; bh[2 * p + 1][1] = rh[3];
            }
#pragma unroll
            for (int mt = 0; mt < 2; mt++)
#pragma unroll
                for (int nt = 0; nt < 4; nt++)
                    mma_f16(acc[mt][nt], ah[mt], bh[nt]);
        }
    };

    load_A_regs(0);
    cp_B(0, 0);
    store_A(0);
    CP_WAIT0();
    __syncthreads();

    for (int ch = 0; ch < 16; ch++) {
        const int cur = ch & 1;
        if (ch < 15) {
            cp_B(ch + 1, cur ^ 1);
            load_A_regs(ch + 1);
        }
        do_mma(cur);
        if (ch < 15) {
            store_A(cur ^ 1);
            CP_WAIT0();
        }
        __syncthreads();
    }

#pragma unroll
    for (int mt = 0; mt < 2; mt++) {
        const int row0 = bm + wm + mt * 16 + gq;
#pragma unroll
        for (int nt = 0; nt < 4; nt++) {
            const int col = bn + wn + nt * 8 + tq * 2;
            const float b0 = __ldg(&g.bias[col]);
            const float b1 = __ldg(&g.bias[col + 1]);
            float2 v0 = make_float2(acc[mt][nt][0] + b0, acc[mt][nt][1] + b1);
            float2 v1 = make_float2(acc[mt][nt][2] + b0, acc[mt][nt][3] + b1);
            *(float2*)&g.C[(size_t)row0 * ldc + col]       = v0;
            *(float2*)&g.C[(size_t)(row0 + 8) * ldc + col] = v1;
        }
    }
}

__global__ __launch_bounds__(256)
void gemm3_kernel(GArgs p0, GArgs p1, GArgs p2, int ldc)
{
    extern __shared__ __half sm[];
    GArgs p = (blockIdx.z == 0) ? p0 : (blockIdx.z == 1) ? p1 : p2;
    gemm_body(p, ldc, blockIdx.x * 128, blockIdx.y * 64, sm);
}
__global__ __launch_bounds__(256)
void gemm1_kernel(GArgs p, int ldc)
{
    extern __shared__ __half sm[];
    gemm_body(p, ldc, blockIdx.x * 128, blockIdx.y * 64, sm);
}

// ---------------------------------------------------------------------------
// Tensor-core attention middle stage. One CTA (128 thr, 4 warps) per group n.
//   S = 0.25 * Qg^T Kg (64x64, K=16), masked, f16;  X[n, h*64+i] = (S @ Vg^T)[i,h]
// Warp w handles S/X rows i in [16w, 16w+16).
// ---------------------------------------------------------------------------
#define QT_STR 24     // Qt/Kt row stride in halves (rows = i/j, cols = hh)
#define VS_STR 72     // Vs/Ss row stride in halves

__global__ __launch_bounds__(128)
void attn_kernel(const float* __restrict__ qp, const float* __restrict__ kp,
                 const float* __restrict__ vp, const int* __restrict__ mask,
                 float* __restrict__ X)
{
    __shared__ __align__(16) __half Qt[64 * QT_STR];  // Qt[i][hh] = Qg[hh][i]
    __shared__ __align__(16) __half Kt[64 * QT_STR];  // Kt[j][hh] = Kg[hh][j]
    __shared__ __align__(16) __half Vs[16 * VS_STR];  // Vs[h][j]  = Vg[h][j]
    __shared__ __align__(16) __half Ss[64 * VS_STR];  // S f16, row-major

    const int n = blockIdx.x, tid = threadIdx.x;
    const int lane = tid & 31, w = tid >> 5;
    const int gq = lane >> 2, tq = lane & 3;
    const int rowA  = (lane & 15);
    const int colA8 = (lane >> 4) * 8;
    const int rowB  = ((lane >> 4) & 1) * 8 + (lane & 7);
    const int colB8 = ((lane >> 3) & 1) * 8;

    const float4* qg = (const float4*)(qp + (size_t)n * NHEAD * HEAD);
    const float4* kg = (const float4*)(kp + (size_t)n * NHEAD * HEAD);
    const float4* vg = (const float4*)(vp + (size_t)n * NHEAD * HEAD);

    // Load + transpose Q,K into [i][hh]; V row-major [h][j]. 2 float4 per thread each.
#pragma unroll
    for (int p = 0; p < 2; p++) {
        int i4 = p * 128 + tid;          // over 256 float4s (16 rows x 16 f4/row)
        int hh = i4 >> 4, c0 = (i4 & 15) * 4;
        float4 q = qg[i4];
        Qt[(c0 + 0) * QT_STR + hh] = __float2half_rn(q.x);
        Qt[(c0 + 1) * QT_STR + hh] = __float2half_rn(q.y);
        Qt[(c0 + 2) * QT_STR + hh] = __float2half_rn(q.z);
        Qt[(c0 + 3) * QT_STR + hh] = __float2half_rn(q.w);
        float4 k = kg[i4];
        Kt[(c0 + 0) * QT_STR + hh] = __float2half_rn(k.x);
        Kt[(c0 + 1) * QT_STR + hh] = __float2half_rn(k.y);
        Kt[(c0 + 2) * QT_STR + hh] = __float2half_rn(k.z);
        Kt[(c0 + 3) * QT_STR + hh] = __float2half_rn(k.w);
        float4 v = vg[i4];
        *(uint2*)&Vs[hh * VS_STR + c0] =
            make_uint2(f16pack(v.x, v.y), f16pack(v.z, v.w));
    }
    __syncthreads();

    // ---- Stage 1: S rows [16w, 16w+16), all 64 cols; K = 16 (one k-step)
    const uint32_t qtB = smem_u32(Qt), ktB = smem_u32(Kt);
    uint32_t aQ[4];
    ldsm_x4(aQ, qtB + (uint32_t)(((16 * w) + rowA) * QT_STR + colA8) * 2);

    float sacc[8][4];
#pragma unroll
    for (int nt = 0; nt < 8; nt++)
#pragma unroll
        for (int r = 0; r < 4; r++) sacc[nt][r] = 0.f;

#pragma unroll
    for (int p = 0; p < 4; p++) {
        uint32_t rb[4];
        ldsm_x4(rb, ktB + (uint32_t)((p * 16 + rowB) * QT_STR + colB8) * 2);
        uint32_t b0[2] = {rb[0], rb[1]}, b1[2] = {rb[2], rb[3]};
        mma_f16(sacc[2 * p],     aQ, b0);
        mma_f16(sacc[2 * p + 1], aQ, b1);
    }

    // scale + mask + f16 store to Ss
    const int i0 = 16 * w + gq;
#pragma unroll
    for (int nt = 0; nt < 8; nt++) {
        const int j0 = nt * 8 + tq * 2;
        int2 m0 = *(const int2*)&mask[i0 * 64 + j0];
        int2 m1 = *(const int2*)&mask[(i0 + 8) * 64 + j0];
        float s0 = sacc[nt][0] * 0.25f; if (m0.x == 0) s0 = -1e30f;
        float s1 = sacc[nt][1] * 0.25f; if (m0.y == 0) s1 = -1e30f;
        float s2 = sacc[nt][2] * 0.25f; if (m1.x == 0) s2 = -1e30f;
        float s3 = sacc[nt][3] * 0.25f; if (m1.y == 0) s3 = -1e30f;
        *(uint32_t*)&Ss[i0 * VS_STR + j0]       = f16pack(s0, s1);
        *(uint32_t*)&Ss[(i0 + 8) * VS_STR + j0] = f16pack(s2, s3);
    }
    __syncthreads();

    // ---- Stage 2: X rows [16w, 16w+16) x 16 heads; K = 64 (4 k-steps)
    const uint32_t ssB = smem_u32(Ss), vsB = smem_u32(Vs);
    float xacc[2][4];
#pragma unroll
    for (int nt = 0; nt < 2; nt++)
#pragma unroll
        for (int r = 0; r < 4; r++) xacc[nt][r] = 0.f;

#pragma unroll
    for (int ks = 0; ks < 4; ks++) {
        uint32_t aS[4], rb[4];
        ldsm_x4(aS, ssB + (uint32_t)((16 * w + rowA) * VS_STR + ks * 16 + colA8) * 2);
        ldsm_x4(rb, vsB + (uint32_t)(rowB * VS_STR + ks * 16 + colB8) * 2);
        uint32_t b0[2] = {rb[0], rb[1]}, b1[2] = {rb[2], rb[3]};
        mma_f16(xacc[0], aS, b0);
        mma_f16(xacc[1], aS, b1);
    }

    // X[n, h*64 + i]
    float* Xn = X + (size_t)n * D_MODEL;
#pragma unroll
    for (int nt = 0; nt < 2; nt++) {
        const int h0 = nt * 8 + tq * 2;
        Xn[h0 * 64 + i0]           = xacc[nt][0];
        Xn[(h0 + 1) * 64 + i0]     = xacc[nt][1];
        Xn[h0 * 64 + i0 + 8]       = xacc[nt][2];
        Xn[(h0 + 1) * 64 + i0 + 8] = xacc[nt][3];
    }
}

// ---------------------------------------------------------------------------
extern "C" void kernel_launch(void* const* d_in, const int* in_sizes, int n_in,
                              void* d_out, int out_size)
{
    const float* query = (const float*)d_in[0];
    const float* key   = (const float*)d_in[1];
    const float* value = (const float*)d_in[2];
    const int*   mask  = (const int*)  d_in[3];
    const float* Wq    = (const float*)d_in[4];
    const float* bq    = (const float*)d_in[5];
    const float* Wk    = (const float*)d_in[6];
    const float* bk    = (const float*)d_in[7];
    const float* Wv    = (const float*)d_in[8];
    const float* bv    = (const float*)d_in[9];
    const float* Wp    = (const float*)d_in[10];
    const float* bp    = (const float*)d_in[11];
    float* out = (float*)d_out;

    float *qp, *kp, *vp, *xg;
    cudaGetSymbolAddress((void**)&qp, g_qp);
    cudaGetSymbolAddress((void**)&kp, g_kp);
    cudaGetSymbolAddress((void**)&vp, g_vp);
    cudaGetSymbolAddress((void**)&xg, g_x);
    __half *wq, *wk, *wv, *wp;
    cudaGetSymbolAddress((void**)&wq, g_wq);
    cudaGetSymbolAddress((void**)&wk, g_wk);
    cudaGetSymbolAddress((void**)&wv, g_wv);
    cudaGetSymbolAddress((void**)&wp, g_wp);

    cudaFuncSetAttribute(gemm3_kernel, cudaFuncAttributeMaxDynamicSharedMemorySize, SM_BYTES);
    cudaFuncSetAttribute(gemm1_kernel, cudaFuncAttributeMaxDynamicSharedMemorySize, SM_BYTES);

    // Weight prep (tiled transpose + f16 round): one merged launch + Wp
    wprep3_kernel<<<dim3(HEAD / 32, D_MODEL / 32, 3), dim3(32, 8)>>>(Wq, wq, Wk, wk, Wv, wv);
    wprep1_kernel<<<dim3(D_MODEL / 32, D_MODEL / 32), dim3(32, 8)>>>(Wp, wp);

    // Merged projections: (16384 x 1024) @ (1024 x 64) + bias, x3
    GArgs pq = {query, wq, bq, qp};
    GArgs pk = {key,   wk, bk, kp};
    GArgs pv = {value, wv, bv, vp};
    gemm3_kernel<<<dim3(ROWS / 128, 1, 3), 256, SM_BYTES>>>(pq, pk, pv, HEAD);

    // Attention middle stage -> X (1024 x 1024), tensor cores
    attn_kernel<<<NGRP, 128>>>(qp, kp, vp, mask, xg);

    // Output projection: (1024 x 1024) @ (1024 x 1024) + bias
    GArgs pp = {xg, wp, bp, out};
    gemm1_kernel<<<dim3(NGRP / 128, D_MODEL / 64), 256, SM_BYTES>>>(pp, D_MODEL);
}

// round 9
// speedup vs baseline: 6.1498x; 1.0276x over previous
#include <cuda_runtime.h>
#include <cuda_fp16.h>
#include <cstdint>

// Problem constants (fixed by reference setup_inputs)
#define D_MODEL 1024
#define HEAD    64
#define NHEAD   16
#define ROWS    16384   // B*S
#define NGRP    1024    // ROWS/NHEAD

// ---------------------------------------------------------------------------
// Scratch (device globals — no allocation allowed)
// ---------------------------------------------------------------------------
__device__ __align__(128) __half g_qp[ROWS * HEAD];   // f16 projections
__device__ __align__(128) __half g_kp[ROWS * HEAD];
__device__ __align__(128) __half g_vp[ROWS * HEAD];
__device__ __align__(128) __half g_x [NGRP * D_MODEL]; // f16, layout [n][i*16+h]

// f16 weights, transposed: [N, K=1024] (k-major rows). g_wp rows use permuted K.
__device__ __align__(128) __half g_wq[HEAD * D_MODEL];
__device__ __align__(128) __half g_wk[HEAD * D_MODEL];
__device__ __align__(128) __half g_wv[HEAD * D_MODEL];
__device__ __align__(128) __half g_wp[D_MODEL * D_MODEL];

// ---------------------------------------------------------------------------
// PTX helpers (sm_80 baseline features only — safe for compute_103 target)
// ---------------------------------------------------------------------------
__device__ __forceinline__ uint32_t smem_u32(const void* p) {
    uint32_t a;
    asm("{ .reg .u64 t; cvta.to.shared.u64 t, %1; cvt.u32.u64 %0, t; }" : "=r"(a) : "l"(p));
    return a;
}
__device__ __forceinline__ void mma_f16(float* d, const uint32_t* a, const uint32_t* b) {
    asm volatile(
        "mma.sync.aligned.m16n8k16.row.col.f32.f16.f16.f32 "
        "{%0,%1,%2,%3}, {%4,%5,%6,%7}, {%8,%9}, {%0,%1,%2,%3};\n"
        : "+f"(d[0]), "+f"(d[1]), "+f"(d[2]), "+f"(d[3])
        : "r"(a[0]), "r"(a[1]), "r"(a[2]), "r"(a[3]), "r"(b[0]), "r"(b[1]));
}
__device__ __forceinline__ void ldsm_x4(uint32_t* r, uint32_t addr) {
    asm volatile("ldmatrix.sync.aligned.m8n8.x4.shared.b16 {%0,%1,%2,%3}, [%4];"
                 : "=r"(r[0]), "=r"(r[1]), "=r"(r[2]), "=r"(r[3]) : "r"(addr));
}
__device__ __forceinline__ void cp_async16(uint32_t dst, const void* src) {
    asm volatile("cp.async.cg.shared.global [%0], [%1], 16;" :: "r"(dst), "l"(src));
}
#define CP_COMMIT() asm volatile("cp.async.commit_group;")
#define CP_WAIT0()  asm volatile("cp.async.wait_group 0;" ::: "memory")

__device__ __forceinline__ uint32_t f16pack(float x, float y) {
    __half2 h = __floats2half2_rn(x, y);
    return *reinterpret_cast<uint32_t*>(&h);
}

// ---------------------------------------------------------------------------
// Weight prep (Q/K/V): W[K,N] fp32 -> Wt [N,K] f16 (transpose + round)
// ---------------------------------------------------------------------------
__device__ __forceinline__
void wprep_body(const float* __restrict__ W, __half* __restrict__ Bt, int N)
{
    __shared__ float t[32][33];
    const int n0 = blockIdx.x * 32, k0 = blockIdx.y * 32;
    const int tx = threadIdx.x, ty = threadIdx.y;
#pragma unroll
    for (int j = 0; j < 4; j++)
        t[ty + 8 * j][tx] = W[(size_t)(k0 + ty + 8 * j) * N + n0 + tx];
    __syncthreads();
#pragma unroll
    for (int j = 0; j < 4; j++) {
        size_t o = (size_t)(n0 + ty + 8 * j) * 1024 + k0 + tx;
        Bt[o] = __float2half_rn(t[tx][ty + 8 * j]);
    }
}
__global__ __launch_bounds__(256)
void wprep3_kernel(const float* W0, __half* B0, const float* W1, __half* B1,
                   const float* W2, __half* B2)
{
    if (blockIdx.z == 0)      wprep_body(W0, B0, HEAD);
    else if (blockIdx.z == 1) wprep_body(W1, B1, HEAD);
    else                      wprep_body(W2, B2, HEAD);
}

// Wp prep with K-permutation: Bt[n][k'] = Wp[k][n], k' = (k&63)*16 + (k>>6)
// (matches X stored as [n][i*16+h])
__global__ __launch_bounds__(256)
void wprep1_kernel(const float* __restrict__ W, __half* __restrict__ Bt)
{
    __shared__ float t[32][33];
    const int n0 = blockIdx.x * 32, kp0 = blockIdx.y * 32;
    const int tx = threadIdx.x, ty = threadIdx.y;
#pragma unroll
    for (int j = 0; j < 4; j++) {
        int l = ty + 8 * j;
        int kpr = kp0 + l;                          // k' index
        int k = (kpr & 15) * 64 + (kpr >> 4);       // original k = h*64+i
        t[l][tx] = W[(size_t)k * 1024 + n0 + tx];
    }
    __syncthreads();
#pragma unroll
    for (int j = 0; j < 4; j++) {
        size_t o = (size_t)(n0 + ty + 8 * j) * 1024 + kp0 + tx;
        Bt[o] = __float2half_rn(t[tx][ty + 8 * j]);
    }
}

// ---------------------------------------------------------------------------
// Common GEMM tile config: BM=128, BN=64, BK=64, 256 threads = 8 warps (4Mx2N)
// ---------------------------------------------------------------------------
#define PADK 72                         // f16 elems per smem row (144 B)
#define OFF_A  0
#define OFF_B  (128 * PADK)
#define STAGE_ELEMS (128 * PADK + 64 * PADK)           // 13824 halves
#define SM_BYTES (2 * STAGE_ELEMS * 2)                 // 55296

// ---- Projection GEMM: A fp32 -> f16 on the fly, C written f16 -------------
struct PArgs {
    const float* A;
    const __half* B;
    const float* bias;
    __half* C;
};

__device__ __forceinline__
void gemm_proj_body(const PArgs& g, int ldc, int bm, int bn, __half* sm)
{
    const uint32_t sb = smem_u32(sm);
    const int tid  = threadIdx.x;
    const int lane = tid & 31, w = tid >> 5;
    const int gq = lane >> 2, tq = lane & 3;
    const int wm = (w >> 1) * 32, wn = (w & 1) * 32;

    const int rowA  = (lane & 15);
    const int colA8 = (lane >> 4) * 8;
    const int rowB  = ((lane >> 4) & 1) * 8 + (lane & 7);
    const int colB8 = ((lane >> 3) & 1) * 8;

    float acc[2][4][4];
#pragma unroll
    for (int mt = 0; mt < 2; mt++)
#pragma unroll
        for (int nt = 0; nt < 4; nt++)
#pragma unroll
            for (int r = 0; r < 4; r++) acc[mt][nt][r] = 0.f;

    float4 aR[8];

    auto load_A_regs = [&](int ch) {
        const int k0 = ch * 64;
#pragma unroll
        for (int p = 0; p < 8; p++) {
            int idx = p * 256 + tid;
            int r = idx >> 4, c4 = idx & 15;
            aR[p] = *(const float4*)&g.A[(size_t)(bm + r) * 1024 + k0 + c4 * 4];
        }
    };
    auto store_A = [&](int stg) {
        __half* A = sm + stg * STAGE_ELEMS + OFF_A;
#pragma unroll
        for (int p = 0; p < 8; p++) {
            int idx = p * 256 + tid;
            int r = idx >> 4, c4 = idx & 15;
            uint32_t h01 = f16pack(aR[p].x, aR[p].y);
            uint32_t h23 = f16pack(aR[p].z, aR[p].w);
            *(uint2*)(A + r * PADK + c4 * 4) = make_uint2(h01, h23);
        }
    };
    auto cp_B = [&](int ch, int stg) {
        const int k0 = ch * 64;
        const uint32_t bd = sb + (stg * STAGE_ELEMS + OFF_B) * 2;
#pragma unroll
        for (int p = 0; p < 2; p++) {
            int idx = p * 256 + tid;
            int r = idx >> 3, c8 = idx & 7;
            size_t off = (size_t)(bn + r) * 1024 + k0 + c8 * 8;
            cp_async16(bd + (uint32_t)(r * 144 + c8 * 16), g.B + off);
        }
        CP_COMMIT();
    };
    auto do_mma = [&](int stg) {
        const uint32_t base = sb + (stg * STAGE_ELEMS) * 2;
        const uint32_t aB = base + OFF_A * 2;
        const uint32_t bB = base + OFF_B * 2;
#pragma unroll
        for (int ks = 0; ks < 4; ks++) {
            const int kk = ks * 16;
            uint32_t ah[2][4], bh[4][2];
#pragma unroll
            for (int mt = 0; mt < 2; mt++) {
                uint32_t off = (uint32_t)((wm + mt * 16 + rowA) * 144 + (kk + colA8) * 2);
                ldsm_x4(ah[mt], aB + off);
            }
#pragma unroll
            for (int p = 0; p < 2; p++) {
                uint32_t off = (uint32_t)((wn + p * 16 + rowB) * 144 + (kk + colB8) * 2);
                uint32_t rh[4];
                ldsm_x4(rh, bB + off);
                bh[2 * p][0] = rh[0]; bh[2 * p][1] = rh[1];
                bh[2 * p + 1][0] = rh[2]; bh[2 * p + 1][1] = rh[3];
            }
#pragma unroll
            for (int mt = 0; mt < 2; mt++)
#pragma unroll
                for (int nt = 0; nt < 4; nt++)
                    mma_f16(acc[mt][nt], ah[mt], bh[nt]);
        }
    };

    load_A_regs(0);
    cp_B(0, 0);
    store_A(0);
    CP_WAIT0();
    __syncthreads();

    for (int ch = 0; ch < 16; ch++) {
        const int cur = ch & 1;
        if (ch < 15) {
            cp_B(ch + 1, cur ^ 1);
            load_A_regs(ch + 1);
        }
        do_mma(cur);
        if (ch < 15) {
            store_A(cur ^ 1);
            CP_WAIT0();
        }
        __syncthreads();
    }

    // epilogue: bias + f16 store
#pragma unroll
    for (int mt = 0; mt < 2; mt++) {
        const int row0 = bm + wm + mt * 16 + gq;
#pragma unroll
        for (int nt = 0; nt < 4; nt++) {
            const int col = bn + wn + nt * 8 + tq * 2;
            const float b0 = __ldg(&g.bias[col]);
            const float b1 = __ldg(&g.bias[col + 1]);
            *(uint32_t*)&g.C[(size_t)row0 * ldc + col] =
                f16pack(acc[mt][nt][0] + b0, acc[mt][nt][1] + b1);
            *(uint32_t*)&g.C[(size_t)(row0 + 8) * ldc + col] =
                f16pack(acc[mt][nt][2] + b0, acc[mt][nt][3] + b1);
        }
    }
}

__global__ __launch_bounds__(256)
void gemm3_kernel(PArgs p0, PArgs p1, PArgs p2, int ldc)
{
    extern __shared__ __half sm[];
    PArgs p = (blockIdx.z == 0) ? p0 : (blockIdx.z == 1) ? p1 : p2;
    gemm_proj_body(p, ldc, blockIdx.x * 128, blockIdx.y * 64, sm);
}

// ---- Output GEMM: A f16 (cp.async), C fp32 + bias --------------------------
__global__ __launch_bounds__(256)
void gemm_out_kernel(const __half* __restrict__ A, const __half* __restrict__ B,
                     const float* __restrict__ bias, float* __restrict__ C, int ldc)
{
    extern __shared__ __half sm[];
    const uint32_t sb = smem_u32(sm);
    const int tid  = threadIdx.x;
    const int lane = tid & 31, w = tid >> 5;
    const int gq = lane >> 2, tq = lane & 3;
    const int wm = (w >> 1) * 32, wn = (w & 1) * 32;
    const int bm = blockIdx.x * 128, bn = blockIdx.y * 64;

    const int rowA  = (lane & 15);
    const int colA8 = (lane >> 4) * 8;
    const int rowB  = ((lane >> 4) & 1) * 8 + (lane & 7);
    const int colB8 = ((lane >> 3) & 1) * 8;

    float acc[2][4][4];
#pragma unroll
    for (int mt = 0; mt < 2; mt++)
#pragma unroll
        for (int nt = 0; nt < 4; nt++)
#pragma unroll
            for (int r = 0; r < 4; r++) acc[mt][nt][r] = 0.f;

    auto cp_stage = [&](int ch, int stg) {
        const int k0 = ch * 64;
        const uint32_t ad = sb + (stg * STAGE_ELEMS + OFF_A) * 2;
        const uint32_t bd = sb + (stg * STAGE_ELEMS + OFF_B) * 2;
#pragma unroll
        for (int p = 0; p < 4; p++) {
            int idx = p * 256 + tid;
            int r = idx >> 3, c8 = idx & 7;
            cp_async16(ad + (uint32_t)(r * 144 + c8 * 16),
                       A + (size_t)(bm + r) * 1024 + k0 + c8 * 8);
        }
#pragma unroll
        for (int p = 0; p < 2; p++) {
            int idx = p * 256 + tid;
            int r = idx >> 3, c8 = idx & 7;
            cp_async16(bd + (uint32_t)(r * 144 + c8 * 16),
                       B + (size_t)(bn + r) * 1024 + k0 + c8 * 8);
        }
        CP_COMMIT();
    };
    auto do_mma = [&](int stg) {
        const uint32_t base = sb + (stg * STAGE_ELEMS) * 2;
        const uint32_t aB = base + OFF_A * 2;
        const uint32_t bB = base + OFF_B * 2;
#pragma unroll
        for (int ks = 0; ks < 4; ks++) {
            const int kk = ks * 16;
            uint32_t ah[2][4], bh[4][2];
#pragma unroll
            for (int mt = 0; mt < 2; mt++) {
                uint32_t off = (uint32_t)((wm + mt * 16 + rowA) * 144 + (kk + colA8) * 2);
                ldsm_x4(ah[mt], aB + off);
            }
#pragma unroll
            for (int p = 0; p < 2; p++) {
                uint32_t off = (uint32_t)((wn + p * 16 + rowB) * 144 + (kk + colB8) * 2);
                uint32_t rh[4];
                ldsm_x4(rh, bB + off);
                bh[2 * p][0] = rh[0]; bh[2 * p][1] = rh[1];
                bh[2 * p + 1][0] = rh[2]; bh[2 * p + 1][1] = rh[3];
            }
#pragma unroll
            for (int mt = 0; mt < 2; mt++)
#pragma unroll
                for (int nt = 0; nt < 4; nt++)
                    mma_f16(acc[mt][nt], ah[mt], bh[nt]);
        }
    };

    cp_stage(0, 0);
    CP_WAIT0();
    __syncthreads();

    for (int ch = 0; ch < 16; ch++) {
        const int cur = ch & 1;
        if (ch < 15) cp_stage(ch + 1, cur ^ 1);
        do_mma(cur);
        if (ch < 15) CP_WAIT0();
        __syncthreads();
    }

#pragma unroll
    for (int mt = 0; mt < 2; mt++) {
        const int row0 = bm + wm + mt * 16 + gq;
#pragma unroll
        for (int nt = 0; nt < 4; nt++) {
            const int col = bn + wn + nt * 8 + tq * 2;
            const float b0 = __ldg(&bias[col]);
            const float b1 = __ldg(&bias[col + 1]);
            float2 v0 = make_float2(acc[mt][nt][0] + b0, acc[mt][nt][1] + b1);
            float2 v1 = make_float2(acc[mt][nt][2] + b0, acc[mt][nt][3] + b1);
            *(float2*)&C[(size_t)row0 * ldc + col]       = v0;
            *(float2*)&C[(size_t)(row0 + 8) * ldc + col] = v1;
        }
    }
}

// ---------------------------------------------------------------------------
// Tensor-core attention middle stage. One CTA (128 thr, 4 warps) per group n.
//   S = 0.25 * Qg^T Kg (64x64, K=16), masked, f16; X'[n][i*16+h] = (S @ Vg^T)[i,h]
// Inputs f16, output f16 (permuted layout matching g_wp's K-permutation).
// ---------------------------------------------------------------------------
#define QT_STR 24     // Qt/Kt row stride in halves (rows = i/j, cols = hh)
#define VS_STR 72     // Vs/Ss row stride in halves

__global__ __launch_bounds__(128)
void attn_kernel(const __half* __restrict__ qp, const __half* __restrict__ kp,
                 const __half* __restrict__ vp, const int* __restrict__ mask,
                 __half* __restrict__ X)
{
    __shared__ __align__(16) __half Qt[64 * QT_STR];  // Qt[i][hh] = Qg[hh][i]
    __shared__ __align__(16) __half Kt[64 * QT_STR];  // Kt[j][hh] = Kg[hh][j]
    __shared__ __align__(16) __half Vs[16 * VS_STR];  // Vs[h][j]  = Vg[h][j]
    __shared__ __align__(16) __half Ss[64 * VS_STR];  // S f16, row-major

    const int n = blockIdx.x, tid = threadIdx.x;
    const int lane = tid & 31, w = tid >> 5;
    const int gq = lane >> 2, tq = lane & 3;
    const int rowA  = (lane & 15);
    const int colA8 = (lane >> 4) * 8;
    const int rowB  = ((lane >> 4) & 1) * 8 + (lane & 7);
    const int colB8 = ((lane >> 3) & 1) * 8;

    const uint4* qg = (const uint4*)(qp + (size_t)n * NHEAD * HEAD);
    const uint4* kg = (const uint4*)(kp + (size_t)n * NHEAD * HEAD);
    const uint4* vg = (const uint4*)(vp + (size_t)n * NHEAD * HEAD);

    // 128 uint4 per tensor: thread tid covers row hh = tid>>3, cols c0..c0+7
    {
        const int hh = tid >> 3, c0 = (tid & 7) * 8;
        union { uint4 u; __half h[8]; } uq, uk;
        uq.u = qg[tid];
        uk.u = kg[tid];
#pragma unroll
        for (int m = 0; m < 8; m++) {
            Qt[(c0 + m) * QT_STR + hh] = uq.h[m];
            Kt[(c0 + m) * QT_STR + hh] = uk.h[m];
        }
        *(uint4*)&Vs[hh * VS_STR + c0] = vg[tid];
    }
    __syncthreads();

    // ---- Stage 1: S rows [16w, 16w+16), all 64 cols; K = 16 (one k-step)
    const uint32_t qtB = smem_u32(Qt), ktB = smem_u32(Kt);
    uint32_t aQ[4];
    ldsm_x4(aQ, qtB + (uint32_t)(((16 * w) + rowA) * QT_STR + colA8) * 2);

    float sacc[8][4];
#pragma unroll
    for (int nt = 0; nt < 8; nt++)
#pragma unroll
        for (int r = 0; r < 4; r++) sacc[nt][r] = 0.f;

#pragma unroll
    for (int p = 0; p < 4; p++) {
        uint32_t rb[4];
        ldsm_x4(rb, ktB + (uint32_t)((p * 16 + rowB) * QT_STR + colB8) * 2);
        uint32_t b0[2] = {rb[0], rb[1]}, b1[2] = {rb[2], rb[3]};
        mma_f16(sacc[2 * p],     aQ, b0);
        mma_f16(sacc[2 * p + 1], aQ, b1);
    }

    // scale + mask + f16 store to Ss
    const int i0 = 16 * w + gq;
#pragma unroll
    for (int nt = 0; nt < 8; nt++) {
        const int j0 = nt * 8 + tq * 2;
        int2 m0 = *(const int2*)&mask[i0 * 64 + j0];
        int2 m1 = *(const int2*)&mask[(i0 + 8) * 64 + j0];
        float s0 = sacc[nt][0] * 0.25f; if (m0.x == 0) s0 = -1e30f;
        float s1 = sacc[nt][1] * 0.25f; if (m0.y == 0) s1 = -1e30f;
        float s2 = sacc[nt][2] * 0.25f; if (m1.x == 0) s2 = -1e30f;
        float s3 = sacc[nt][3] * 0.25f; if (m1.y == 0) s3 = -1e30f;
        *(uint32_t*)&Ss[i0 * VS_STR + j0]       = f16pack(s0, s1);
        *(uint32_t*)&Ss[(i0 + 8) * VS_STR + j0] = f16pack(s2, s3);
    }
    __syncthreads();

    // ---- Stage 2: X rows [16w, 16w+16) x 16 heads; K = 64 (4 k-steps)
    const uint32_t ssB = smem_u32(Ss), vsB = smem_u32(Vs);
    float xacc[2][4];
#pragma unroll
    for (int nt = 0; nt < 2; nt++)
#pragma unroll
        for (int r = 0; r < 4; r++) xacc[nt][r] = 0.f;

#pragma unroll
    for (int ks = 0; ks < 4; ks++) {
        uint32_t aS[4], rb[4];
        ldsm_x4(aS, ssB + (uint32_t)((16 * w + rowA) * VS_STR + ks * 16 + colA8) * 2);
        ldsm_x4(rb, vsB + (uint32_t)(rowB * VS_STR + ks * 16 + colB8) * 2);
        uint32_t b0[2] = {rb[0], rb[1]}, b1[2] = {rb[2], rb[3]};
        mma_f16(xacc[0], aS, b0);
        mma_f16(xacc[1], aS, b1);
    }

    // X'[n][i*16 + h], f16 (pairs over consecutive h)
    __half* Xn = X + (size_t)n * D_MODEL;
#pragma unroll
    for (int nt = 0; nt < 2; nt++) {
        const int h0 = nt * 8 + tq * 2;
        *(uint32_t*)&Xn[i0 * 16 + h0]       = f16pack(xacc[nt][0], xacc[nt][1]);
        *(uint32_t*)&Xn[(i0 + 8) * 16 + h0] = f16pack(xacc[nt][2], xacc[nt][3]);
    }
}

// ---------------------------------------------------------------------------
extern "C" void kernel_launch(void* const* d_in, const int* in_sizes, int n_in,
                              void* d_out, int out_size)
{
    const float* query = (const float*)d_in[0];
    const float* key   = (const float*)d_in[1];
    const float* value = (const float*)d_in[2];
    const int*   mask  = (const int*)  d_in[3];
    const float* Wq    = (const float*)d_in[4];
    const float* bq    = (const float*)d_in[5];
    const float* Wk    = (const float*)d_in[6];
    const float* bk    = (const float*)d_in[7];
    const float* Wv    = (const float*)d_in[8];
    const float* bv    = (const float*)d_in[9];
    const float* Wp    = (const float*)d_in[10];
    const float* bp    = (const float*)d_in[11];
    float* out = (float*)d_out;

    __half *qp, *kp, *vp, *xg, *wq, *wk, *wv, *wp;
    cudaGetSymbolAddress((void**)&qp, g_qp);
    cudaGetSymbolAddress((void**)&kp, g_kp);
    cudaGetSymbolAddress((void**)&vp, g_vp);
    cudaGetSymbolAddress((void**)&xg, g_x);
    cudaGetSymbolAddress((void**)&wq, g_wq);
    cudaGetSymbolAddress((void**)&wk, g_wk);
    cudaGetSymbolAddress((void**)&wv, g_wv);
    cudaGetSymbolAddress((void**)&wp, g_wp);

    cudaFuncSetAttribute(gemm3_kernel, cudaFuncAttributeMaxDynamicSharedMemorySize, SM_BYTES);
    cudaFuncSetAttribute(gemm_out_kernel, cudaFuncAttributeMaxDynamicSharedMemorySize, SM_BYTES);

    // Weight prep
    wprep3_kernel<<<dim3(HEAD / 32, D_MODEL / 32, 3), dim3(32, 8)>>>(Wq, wq, Wk, wk, Wv, wv);
    wprep1_kernel<<<dim3(D_MODEL / 32, D_MODEL / 32), dim3(32, 8)>>>(Wp, wp);

    // Merged projections: (16384 x 1024) @ (1024 x 64) + bias, x3 -> f16
    PArgs pq = {query, wq, bq, qp};
    PArgs pk = {key,   wk, bk, kp};
    PArgs pv = {value, wv, bv, vp};
    gemm3_kernel<<<dim3(ROWS / 128, 1, 3), 256, SM_BYTES>>>(pq, pk, pv, HEAD);

    // Attention middle stage -> X' f16 [n][i*16+h]
    attn_kernel<<<NGRP, 128>>>(qp, kp, vp, mask, xg);

    // Output projection: (1024 x 1024) @ (1024 x 1024) + bias (fp32 out)
    gemm_out_kernel<<<dim3(NGRP / 128, D_MODEL / 64), 256, SM_BYTES>>>(xg, wp, bp, out, D_MODEL);
}